// round 1
// baseline (speedup 1.0000x reference)
#include <cuda_runtime.h>
#include <cstdint>
#include <cstddef>

#define BROWS 8192
#define DEMB  1152
#define DHID  32768
#define TOPK  64

// ---------------- scratch (device globals: sanctioned scratch path) ----------
static __device__ float g_x[(size_t)BROWS * DHID];     // 1 GiB: relu(encoder) acts
static __device__ float g_wdt[(size_t)DHID * DEMB];    // W_down^T  [32768,1152]
static __device__ float g_val[BROWS * TOPK];
static __device__ int   g_idx[BROWS * TOPK];

// ---------------- kernel 1: x = relu(embs @ W_up^T + b_up) -------------------
// A: [8192,1152] row-major, W: [32768,1152] row-major (both K-contiguous, NT GEMM)
__global__ __launch_bounds__(256, 2) void gemm_relu_kernel(
    const float* __restrict__ A, const float* __restrict__ W,
    const float* __restrict__ bias) {
  __shared__ float As[16][128];
  __shared__ float Bs[16][128];
  const int bm = blockIdx.y, bn = blockIdx.x;
  const int tid  = threadIdx.x;
  const int lrow = tid >> 2;            // 0..63
  const int lcol = (tid & 3) << 2;      // 0,4,8,12
  const int ty = tid >> 4, tx = tid & 15;

  const float* Ab = A + (size_t)bm * 128 * DEMB;
  const float* Wb = W + (size_t)bn * 128 * DEMB;

  float acc[8][8];
#pragma unroll
  for (int i = 0; i < 8; i++)
#pragma unroll
    for (int j = 0; j < 8; j++) acc[i][j] = 0.f;

  for (int k0 = 0; k0 < DEMB; k0 += 16) {
#pragma unroll
    for (int i = 0; i < 2; i++) {
      int r = lrow + (i << 6);
      float4 av = *reinterpret_cast<const float4*>(Ab + (size_t)r * DEMB + k0 + lcol);
      As[lcol + 0][r] = av.x; As[lcol + 1][r] = av.y;
      As[lcol + 2][r] = av.z; As[lcol + 3][r] = av.w;
      float4 bv = *reinterpret_cast<const float4*>(Wb + (size_t)r * DEMB + k0 + lcol);
      Bs[lcol + 0][r] = bv.x; Bs[lcol + 1][r] = bv.y;
      Bs[lcol + 2][r] = bv.z; Bs[lcol + 3][r] = bv.w;
    }
    __syncthreads();
#pragma unroll
    for (int kk = 0; kk < 16; kk++) {
      float af[8], bf[8];
      *reinterpret_cast<float4*>(&af[0]) = *reinterpret_cast<const float4*>(&As[kk][ty * 8]);
      *reinterpret_cast<float4*>(&af[4]) = *reinterpret_cast<const float4*>(&As[kk][ty * 8 + 4]);
      *reinterpret_cast<float4*>(&bf[0]) = *reinterpret_cast<const float4*>(&Bs[kk][tx * 8]);
      *reinterpret_cast<float4*>(&bf[4]) = *reinterpret_cast<const float4*>(&Bs[kk][tx * 8 + 4]);
#pragma unroll
      for (int i = 0; i < 8; i++)
#pragma unroll
        for (int j = 0; j < 8; j++)
          acc[i][j] = fmaf(af[i], bf[j], acc[i][j]);
    }
    __syncthreads();
  }

  float bv[8];
  const float* bp = bias + bn * 128 + tx * 8;
#pragma unroll
  for (int j = 0; j < 8; j++) bv[j] = bp[j];

#pragma unroll
  for (int i = 0; i < 8; i++) {
    float* crow = g_x + (size_t)(bm * 128 + ty * 8 + i) * DHID + bn * 128 + tx * 8;
    float4 o0, o1;
    o0.x = fmaxf(acc[i][0] + bv[0], 0.f);
    o0.y = fmaxf(acc[i][1] + bv[1], 0.f);
    o0.z = fmaxf(acc[i][2] + bv[2], 0.f);
    o0.w = fmaxf(acc[i][3] + bv[3], 0.f);
    o1.x = fmaxf(acc[i][4] + bv[4], 0.f);
    o1.y = fmaxf(acc[i][5] + bv[5], 0.f);
    o1.z = fmaxf(acc[i][6] + bv[6], 0.f);
    o1.w = fmaxf(acc[i][7] + bv[7], 0.f);
    *reinterpret_cast<float4*>(crow)     = o0;
    *reinterpret_cast<float4*>(crow + 4) = o1;
  }
}

// ---------------- kernel 2: transpose W_down [1152,32768] -> [32768,1152] ----
__global__ void transpose_kernel(const float* __restrict__ W) {
  __shared__ float tile[32][33];
  int x = blockIdx.x * 32 + threadIdx.x;  // h (32768)
  int y = blockIdx.y * 32 + threadIdx.y;  // e (1152), blockDim 32x8
#pragma unroll
  for (int j = 0; j < 32; j += 8)
    tile[threadIdx.y + j][threadIdx.x] = W[(size_t)(y + j) * DHID + x];
  __syncthreads();
  int xo = blockIdx.y * 32 + threadIdx.x; // e
  int yo = blockIdx.x * 32 + threadIdx.y; // h
#pragma unroll
  for (int j = 0; j < 32; j += 8)
    g_wdt[(size_t)(yo + j) * DEMB + xo] = tile[threadIdx.x][threadIdx.y + j];
}

// ---------------- kernel 3: per-row top-64 via 3-pass radix select -----------
// Nonnegative floats: uint bit pattern is order-preserving.
__device__ __forceinline__ void find_kth(unsigned* hist, int nb, unsigned r,
                                         unsigned* part,
                                         unsigned* selbin, unsigned* need,
                                         int tid) {
  unsigned base = (unsigned)tid * 8;
  unsigned ps = 0;
  if (base < (unsigned)nb) {
#pragma unroll
    for (int j = 0; j < 8; j++) ps += hist[base + j];
  }
  part[tid] = ps;
  __syncthreads();
  if (tid == 0) {                           // suffix-sum over 512 partials
    unsigned run = 0;
    for (int t = 511; t >= 0; t--) { unsigned p = part[t]; part[t] = run; run += p; }
  }
  __syncthreads();
  if (base < (unsigned)nb) {
    unsigned cum = part[tid];               // count in bins > base+7
    for (int j = 7; j >= 0; j--) {
      unsigned h = hist[base + j];
      if (cum < r && cum + h >= r) { *selbin = base + j; *need = r - cum; }
      cum += h;
    }
  }
  __syncthreads();
}

__global__ __launch_bounds__(512) void topk_kernel() {
  extern __shared__ float sv[];                      // 32768 floats (128 KB)
  unsigned* hist = reinterpret_cast<unsigned*>(sv + DHID);  // 4096 bins (16 KB)
  __shared__ unsigned part[512];
  __shared__ unsigned s_selbin, s_need, s_cnt;

  const int row = blockIdx.x;
  const int tid = threadIdx.x;
  const float* src = g_x + (size_t)row * DHID;

  // stage row in smem (vectorized)
  const float4* s4 = reinterpret_cast<const float4*>(src);
  float4* d4 = reinterpret_cast<float4*>(sv);
  for (int i = tid; i < DHID / 4; i += 512) d4[i] = s4[i];
  __syncthreads();

  // ---- pass A: bits [30:20] (exp + 3 mantissa), 4096 bins ----
  for (int i = tid; i < 4096; i += 512) hist[i] = 0;
  __syncthreads();
  for (int i = tid; i < DHID; i += 512) {
    unsigned u = __float_as_uint(sv[i]);
    atomicAdd(&hist[u >> 20], 1u);
  }
  __syncthreads();
  find_kth(hist, 4096, TOPK + 1, part, &s_selbin, &s_need, tid);
  unsigned binA = s_selbin, rB = s_need;
  __syncthreads();

  // ---- pass B: bits [19:8], 4096 bins, restricted to bin A ----
  for (int i = tid; i < 4096; i += 512) hist[i] = 0;
  __syncthreads();
  for (int i = tid; i < DHID; i += 512) {
    unsigned u = __float_as_uint(sv[i]);
    if ((u >> 20) == binA) atomicAdd(&hist[(u >> 8) & 0xFFF], 1u);
  }
  __syncthreads();
  find_kth(hist, 4096, rB, part, &s_selbin, &s_need, tid);
  unsigned binB = s_selbin, rC = s_need;
  __syncthreads();

  // ---- pass C: bits [7:0], 256 bins, restricted to (A,B) prefix ----
  for (int i = tid; i < 4096; i += 512) hist[i] = 0;
  __syncthreads();
  unsigned pref = (binA << 12) | binB;
  for (int i = tid; i < DHID; i += 512) {
    unsigned u = __float_as_uint(sv[i]);
    if ((u >> 8) == pref) atomicAdd(&hist[u & 0xFF], 1u);
  }
  __syncthreads();
  find_kth(hist, 256, rC, part, &s_selbin, &s_need, tid);
  unsigned thr = (binA << 20) | (binB << 8) | s_selbin;  // exact 65th-largest bits

  // ---- compact strictly-greater elements (count <= 64 guaranteed) ----
  if (tid == 0) s_cnt = 0;
  __syncthreads();
  for (int i = tid; i < DHID; i += 512) {
    unsigned u = __float_as_uint(sv[i]);
    if (u > thr) {
      unsigned p = atomicAdd(&s_cnt, 1u);
      if (p < TOPK) {
        g_idx[row * TOPK + p] = i;
        g_val[row * TOPK + p] = sv[i];
      }
    }
  }
  __syncthreads();
  unsigned cnt = s_cnt;
  for (int j = tid; j < TOPK; j += 512) {
    if ((unsigned)j >= cnt) { g_idx[row * TOPK + j] = 0; g_val[row * TOPK + j] = 0.f; }
  }
}

// ---------------- kernel 4: out = b_down + sum_k val_k * W_down^T[idx_k] -----
__global__ __launch_bounds__(384) void decoder_kernel(
    const float* __restrict__ bdown, float* __restrict__ out) {
  const int b = blockIdx.x;
  const int tid = threadIdx.x;
  __shared__ int   sidx[TOPK];
  __shared__ float sval[TOPK];
  if (tid < TOPK) {
    sidx[tid] = g_idx[b * TOPK + tid];
    sval[tid] = g_val[b * TOPK + tid];
  }
  __syncthreads();

  // bitonic sort by index -> deterministic accumulation order
  for (int k = 2; k <= TOPK; k <<= 1) {
    for (int j = k >> 1; j > 0; j >>= 1) {
      if (tid < TOPK) {
        int ixj = tid ^ j;
        if (ixj > tid) {
          bool up = ((tid & k) == 0);
          int ia = sidx[tid], ib = sidx[ixj];
          bool sw = up ? (ia > ib) : (ia < ib);
          if (sw) {
            sidx[tid] = ib; sidx[ixj] = ia;
            float fa = sval[tid]; sval[tid] = sval[ixj]; sval[ixj] = fa;
          }
        }
      }
      __syncthreads();
    }
  }

  const int e0 = tid, e1 = tid + 384, e2 = tid + 768;
  float a0 = bdown[e0], a1 = bdown[e1], a2 = bdown[e2];
#pragma unroll 4
  for (int k = 0; k < TOPK; k++) {
    float v = sval[k];
    const float* wr = g_wdt + (size_t)sidx[k] * DEMB;
    a0 = fmaf(v, wr[e0], a0);
    a1 = fmaf(v, wr[e1], a1);
    a2 = fmaf(v, wr[e2], a2);
  }
  float* o = out + (size_t)b * DEMB;
  o[e0] = a0; o[e1] = a1; o[e2] = a2;
}

// ---------------- launch ------------------------------------------------------
extern "C" void kernel_launch(void* const* d_in, const int* in_sizes, int n_in,
                              void* d_out, int out_size) {
  const float* embs   = (const float*)d_in[0];
  const float* W_up   = (const float*)d_in[1];
  const float* b_up   = (const float*)d_in[2];
  const float* W_down = (const float*)d_in[3];
  const float* b_down = (const float*)d_in[4];
  float* out = (float*)d_out;

  cudaFuncSetAttribute(topk_kernel, cudaFuncAttributeMaxDynamicSharedMemorySize,
                       (DHID * 4) + (4096 * 4));  // 147456 B

  gemm_relu_kernel<<<dim3(DHID / 128, BROWS / 128), 256>>>(embs, W_up, b_up);
  transpose_kernel<<<dim3(DHID / 32, DEMB / 32), dim3(32, 8)>>>(W_down);
  topk_kernel<<<BROWS, 512, (DHID * 4) + (4096 * 4)>>>();
  decoder_kernel<<<BROWS, 384>>>(b_down, out);
}

// round 9
// speedup vs baseline: 1.9427x; 1.9427x over previous
#include <cuda_runtime.h>
#include <cuda_bf16.h>
#include <cstdint>
#include <cstddef>

#define BROWS 8192
#define DEMB  1152
#define DHID  32768
#define TOPK  64
#define NCAND 256
#define CRANK 160

// GEMM tiling (48KB-safe static smem)
#define BM 128
#define BN 128
#define BK 32
#define KITERS 36                 // 1152/32
#define LDB 80                    // bytes per smem row (64 data + 16 pad)
#define ATILE_B (128 * LDB)       // 10240
#define STAGE_B (2 * ATILE_B)     // 20480 (A+B)
#define GEMM_SMEM (2 * STAGE_B)   // 40960 < 48K

// ---------------- scratch (referenced from DEVICE code only) -------------------
static __device__ __nv_bfloat16 g_ab[(size_t)BROWS * DEMB];
static __device__ __nv_bfloat16 g_wb[(size_t)DHID * DEMB];
static __device__ __nv_bfloat16 g_xb[(size_t)BROWS * DHID];   // approx acts
static __device__ float g_wdt[(size_t)DHID * DEMB];           // W_down^T
static __device__ int   g_cand[(size_t)BROWS * NCAND];
static __device__ int   g_ccnt[BROWS];
static __device__ float g_val[BROWS * TOPK];
static __device__ int   g_idx[BROWS * TOPK];

// ---------------- helpers ------------------------------------------------------
__device__ __forceinline__ uint32_t smem_u32(const void* p) {
  uint32_t a;
  asm("{ .reg .u64 t; cvta.to.shared.u64 t, %1; cvt.u32.u64 %0, t; }" : "=r"(a) : "l"(p));
  return a;
}
__device__ __forceinline__ void cp16(uint32_t dst, const void* src) {
  asm volatile("cp.async.cg.shared.global [%0], [%1], 16;" :: "r"(dst), "l"(src));
}
__device__ __forceinline__ void ldsm4(uint32_t* r, uint32_t addr) {
  asm volatile("ldmatrix.sync.aligned.m8n8.x4.shared.b16 {%0,%1,%2,%3}, [%4];"
               : "=r"(r[0]), "=r"(r[1]), "=r"(r[2]), "=r"(r[3]) : "r"(addr) : "memory");
}
__device__ __forceinline__ void mma16816(float* c, const uint32_t* a,
                                         uint32_t b0, uint32_t b1) {
  asm volatile("mma.sync.aligned.m16n8k16.row.col.f32.bf16.bf16.f32 "
               "{%0,%1,%2,%3}, {%4,%5,%6,%7}, {%8,%9}, {%0,%1,%2,%3};"
               : "+f"(c[0]), "+f"(c[1]), "+f"(c[2]), "+f"(c[3])
               : "r"(a[0]), "r"(a[1]), "r"(a[2]), "r"(a[3]), "r"(b0), "r"(b1));
}
__device__ __forceinline__ void cvt8(const float* __restrict__ src,
                                     __nv_bfloat16* __restrict__ dst, size_t i) {
  float4 a = *reinterpret_cast<const float4*>(src + i);
  float4 b = *reinterpret_cast<const float4*>(src + i + 4);
  __nv_bfloat162 p[4];
  p[0] = __float22bfloat162_rn(make_float2(a.x, a.y));
  p[1] = __float22bfloat162_rn(make_float2(a.z, a.w));
  p[2] = __float22bfloat162_rn(make_float2(b.x, b.y));
  p[3] = __float22bfloat162_rn(make_float2(b.z, b.w));
  *reinterpret_cast<uint4*>(dst + i) = *reinterpret_cast<uint4*>(p);
}

// ---------------- kernel 0a/0b: fp32 -> bf16 (globals referenced in-device) ----
__global__ void cvt_A_kernel(const float* __restrict__ src) {
  size_t i = ((size_t)blockIdx.x * blockDim.x + threadIdx.x) * 8;
  cvt8(src, g_ab, i);
}
__global__ void cvt_W_kernel(const float* __restrict__ src) {
  size_t i = ((size_t)blockIdx.x * blockDim.x + threadIdx.x) * 8;
  cvt8(src, g_wb, i);
}

// ---------------- kernel 1: bf16 mma.sync GEMM ---------------------------------
__device__ __forceinline__ void load_stage(uint32_t sb, int it, int tid,
                                           const __nv_bfloat16* Ag,
                                           const __nv_bfloat16* Bg) {
  if (it < KITERS) {
    uint32_t base = sb + (it & 1) * STAGE_B;
    int k0 = it * BK;
#pragma unroll
    for (int j = 0; j < 4; j++) {
      int c = tid + j * 256;
      int half = c >> 9, jj = c & 511;
      int row = jj >> 2, kc = jj & 3;
      const __nv_bfloat16* src =
          (half ? Bg : Ag) + (size_t)row * DEMB + k0 + kc * 8;
      cp16(base + half * ATILE_B + row * LDB + kc * 16, src);
    }
  }
  asm volatile("cp.async.commit_group;" ::: "memory");
}

__global__ __launch_bounds__(256) void gemm_bf16_kernel(const float* __restrict__ bias) {
  __shared__ __align__(128) char smem[GEMM_SMEM];
  const uint32_t sb = smem_u32(smem);
  const int tid = threadIdx.x, lane = tid & 31, wid = tid >> 5;
  const int bm = blockIdx.x, bn = blockIdx.y;
  const int wm = wid >> 1, wn = wid & 1;   // 4x2 warps, warp tile 32x64

  const __nv_bfloat16* Ag = g_ab + (size_t)bm * BM * DEMB;
  const __nv_bfloat16* Bg = g_wb + (size_t)bn * BN * DEMB;

  float acc[2][8][4];
#pragma unroll
  for (int i = 0; i < 2; i++)
#pragma unroll
    for (int j = 0; j < 8; j++)
#pragma unroll
      for (int q = 0; q < 4; q++) acc[i][j][q] = 0.f;

  load_stage(sb, 0, tid, Ag, Bg);
  load_stage(sb, 1, tid, Ag, Bg);

  const uint32_t rsel = (lane & 15);
  const uint32_t ksel = (lane >> 4) * 16;

  for (int it = 0; it < KITERS; ++it) {
    asm volatile("cp.async.wait_group 1;" ::: "memory");
    __syncthreads();
    const uint32_t Ab = sb + (it & 1) * STAGE_B;
    const uint32_t Bb = Ab + ATILE_B;
#pragma unroll
    for (int ks = 0; ks < 2; ++ks) {
      const uint32_t koff = ks * 32 + ksel;
      uint32_t a0[4], a1[4];
      ldsm4(a0, Ab + (wm * 32 + rsel) * LDB + koff);
      ldsm4(a1, Ab + (wm * 32 + 16 + rsel) * LDB + koff);
      uint32_t bfr[4][4];
#pragma unroll
      for (int nj = 0; nj < 4; nj++)
        ldsm4(bfr[nj], Bb + (wn * 64 + nj * 16 + rsel) * LDB + koff);
#pragma unroll
      for (int nj = 0; nj < 4; nj++) {
        mma16816(acc[0][2 * nj],     a0, bfr[nj][0], bfr[nj][2]);
        mma16816(acc[0][2 * nj + 1], a0, bfr[nj][1], bfr[nj][3]);
        mma16816(acc[1][2 * nj],     a1, bfr[nj][0], bfr[nj][2]);
        mma16816(acc[1][2 * nj + 1], a1, bfr[nj][1], bfr[nj][3]);
      }
    }
    __syncthreads();
    load_stage(sb, it + 2, tid, Ag, Bg);
  }

  // epilogue: bias + relu + bf16 store
  const int mrow0 = bm * 128 + wm * 32;
  const int ncol0 = bn * 128 + wn * 64;
#pragma unroll
  for (int nn = 0; nn < 8; nn++) {
    const int col = ncol0 + nn * 8 + 2 * (lane & 3);
    const float2 bv = *reinterpret_cast<const float2*>(bias + col);
#pragma unroll
    for (int mi = 0; mi < 2; mi++) {
      const int r0 = mrow0 + mi * 16 + (lane >> 2);
      float v0 = fmaxf(acc[mi][nn][0] + bv.x, 0.f);
      float v1 = fmaxf(acc[mi][nn][1] + bv.y, 0.f);
      float v2 = fmaxf(acc[mi][nn][2] + bv.x, 0.f);
      float v3 = fmaxf(acc[mi][nn][3] + bv.y, 0.f);
      __nv_bfloat162 p0 = __float22bfloat162_rn(make_float2(v0, v1));
      __nv_bfloat162 p1 = __float22bfloat162_rn(make_float2(v2, v3));
      *reinterpret_cast<uint32_t*>(g_xb + (size_t)r0 * DHID + col) =
          *reinterpret_cast<uint32_t*>(&p0);
      *reinterpret_cast<uint32_t*>(g_xb + (size_t)(r0 + 8) * DHID + col) =
          *reinterpret_cast<uint32_t*>(&p1);
    }
  }
}

// ---------------- kernel 2: transpose W_down -----------------------------------
__global__ void transpose_kernel(const float* __restrict__ W) {
  __shared__ float tile[32][33];
  int x = blockIdx.x * 32 + threadIdx.x;
  int y = blockIdx.y * 32 + threadIdx.y;
#pragma unroll
  for (int j = 0; j < 32; j += 8)
    tile[threadIdx.y + j][threadIdx.x] = W[(size_t)(y + j) * DHID + x];
  __syncthreads();
  int xo = blockIdx.y * 32 + threadIdx.x;
  int yo = blockIdx.x * 32 + threadIdx.y;
#pragma unroll
  for (int j = 0; j < 32; j += 8)
    g_wdt[(size_t)(yo + j) * DEMB + xo] = tile[threadIdx.x][threadIdx.y + j];
}

// ---------------- kernel 3: candidate selection (rank-160 of x-hat) ------------
__global__ __launch_bounds__(256) void select_kernel() {
  __shared__ unsigned hist[4096];          // bins = u >> 4
  __shared__ unsigned hist16[16];
  __shared__ int s_c1, s_cc;
  __shared__ unsigned s_binA, s_needA, s_thr;

  const int row = blockIdx.x, tid = threadIdx.x;
  const uint4* xr4 = reinterpret_cast<const uint4*>(g_xb + (size_t)row * DHID);

  for (int i = tid; i < 4096; i += 256) hist[i] = 0;
  if (tid < 16) hist16[tid] = 0;
  if (tid == 0) { s_c1 = 0; s_cc = 0; }
  __syncthreads();

  // sweep 1: 4096-bin histogram over elements >= 1.0 (0x3F80)
  int c1 = 0;
  for (int i = tid; i < DHID / 8; i += 256) {
    uint4 v = xr4[i];
    unsigned w[4] = {v.x, v.y, v.z, v.w};
#pragma unroll
    for (int q = 0; q < 4; q++) {
      unsigned u0 = w[q] & 0xFFFFu, u1 = w[q] >> 16;
      if (u0 >= 0x3F80u) { atomicAdd(&hist[u0 >> 4], 1u); c1++; }
      if (u1 >= 0x3F80u) { atomicAdd(&hist[u1 >> 4], 1u); c1++; }
    }
  }
#pragma unroll
  for (int o = 16; o; o >>= 1) c1 += __shfl_xor_sync(0xffffffff, c1, o);
  if ((tid & 31) == 0) atomicAdd(&s_c1, c1);
  __syncthreads();

  if (tid == 0) {
    if (s_c1 >= CRANK) {
      unsigned cum = 0;
      for (int b = 4095; b >= 0; b--) {
        unsigned h = hist[b];
        if (cum + h >= CRANK) { s_binA = (unsigned)b; s_needA = CRANK - cum; break; }
        cum += h;
      }
    } else {
      s_binA = 0xFFFFFFFFu;   // degenerate: take all positives
      s_thr = 1u;
    }
  }
  __syncthreads();
  const unsigned binA = s_binA;

  if (binA != 0xFFFFFFFFu) {
    // sweep 2: refine within binA on low 4 bits
    for (int i = tid; i < DHID / 8; i += 256) {
      uint4 v = xr4[i];
      unsigned w[4] = {v.x, v.y, v.z, v.w};
#pragma unroll
      for (int q = 0; q < 4; q++) {
        unsigned u0 = w[q] & 0xFFFFu, u1 = w[q] >> 16;
        if ((u0 >> 4) == binA) atomicAdd(&hist16[u0 & 15u], 1u);
        if ((u1 >> 4) == binA) atomicAdd(&hist16[u1 & 15u], 1u);
      }
    }
    __syncthreads();
    if (tid == 0) {
      unsigned cum = 0, need = s_needA;
      unsigned thr = binA << 4;
      for (int b = 15; b >= 0; b--) {
        unsigned h = hist16[b];
        if (cum + h >= need) { thr = (binA << 4) | (unsigned)b; break; }
        cum += h;
      }
      s_thr = thr;
    }
    __syncthreads();
  }
  const unsigned thr = s_thr;

  // sweep 3: compact u >= thr
  for (int i = tid; i < DHID / 8; i += 256) {
    uint4 v = xr4[i];
    unsigned w[4] = {v.x, v.y, v.z, v.w};
#pragma unroll
    for (int q = 0; q < 4; q++) {
      unsigned u0 = w[q] & 0xFFFFu, u1 = w[q] >> 16;
      if (u0 >= thr && u0 != 0) {
        int p = atomicAdd(&s_cc, 1);
        if (p < NCAND) g_cand[(size_t)row * NCAND + p] = i * 8 + q * 2;
      }
      if (u1 >= thr && u1 != 0) {
        int p = atomicAdd(&s_cc, 1);
        if (p < NCAND) g_cand[(size_t)row * NCAND + p] = i * 8 + q * 2 + 1;
      }
    }
  }
  __syncthreads();
  if (tid == 0) g_ccnt[row] = (s_cc < NCAND) ? s_cc : NCAND;
}

// ---------------- kernel 4: R1-identical fp32 rescore + exact top-64 -----------
// One THREAD per candidate: strictly sequential k=0..1151 fmaf chain — the exact
// arithmetic of the R1 kernel that passed (agrees with the reference on sub-ulp
// rank-64/65 near-ties, where summation order decides the winner).
__global__ __launch_bounds__(256) void exact_kernel(const float* __restrict__ embs,
                                                    const float* __restrict__ W,
                                                    const float* __restrict__ bup) {
  __shared__ float ar[DEMB];
  __shared__ float sval[NCAND];
  __shared__ int   sidx[NCAND];
  const int row = blockIdx.x, tid = threadIdx.x;

  for (int i = tid; i < DEMB; i += 256) ar[i] = embs[(size_t)row * DEMB + i];
  sval[tid] = -1e30f;
  sidx[tid] = 0;
  __syncthreads();

  const int cnt = g_ccnt[row];
  if (tid < cnt) {
    const int h = g_cand[(size_t)row * NCAND + tid];
    const float* wr = W + (size_t)h * DEMB;
    float acc = 0.f;
#pragma unroll 8
    for (int k = 0; k < DEMB; k++)
      acc = __fmaf_rn(ar[k], __ldg(wr + k), acc);   // sequential, k ascending
    sval[tid] = fmaxf(acc + __ldg(bup + h), 0.f);   // same add/relu order as R1
    sidx[tid] = h;
  }
  __syncthreads();

  // ascending bitonic sort of 256 (val, idx) pairs
  for (int k = 2; k <= NCAND; k <<= 1) {
    for (int j = k >> 1; j > 0; j >>= 1) {
      int ixj = tid ^ j;
      if (ixj > tid) {
        bool up = ((tid & k) == 0);
        float va = sval[tid], vb = sval[ixj];
        bool sw = up ? (va > vb) : (va < vb);
        if (sw) {
          sval[tid] = vb; sval[ixj] = va;
          int t = sidx[tid]; sidx[tid] = sidx[ixj]; sidx[ixj] = t;
        }
      }
      __syncthreads();
    }
  }

  // top-64 at positions 192..255 (ascending); 65th largest at 191
  float thr = sval[191];
  if (tid >= 192) {
    int j = tid - 192;
    bool keep = sval[tid] > thr;
    g_val[row * TOPK + j] = keep ? sval[tid] : 0.f;
    g_idx[row * TOPK + j] = keep ? sidx[tid] : 0;
  }
}

// ---------------- kernel 5: sparse decoder -------------------------------------
__global__ __launch_bounds__(384) void decoder_kernel(
    const float* __restrict__ bdown, float* __restrict__ out) {
  const int b = blockIdx.x;
  const int tid = threadIdx.x;
  __shared__ int   sidx[TOPK];
  __shared__ float sval[TOPK];
  if (tid < TOPK) {
    sidx[tid] = g_idx[b * TOPK + tid];
    sval[tid] = g_val[b * TOPK + tid];
  }
  __syncthreads();

  for (int k = 2; k <= TOPK; k <<= 1) {
    for (int j = k >> 1; j > 0; j >>= 1) {
      if (tid < TOPK) {
        int ixj = tid ^ j;
        if (ixj > tid) {
          bool up = ((tid & k) == 0);
          int ia = sidx[tid], ib = sidx[ixj];
          bool sw = up ? (ia > ib) : (ia < ib);
          if (sw) {
            sidx[tid] = ib; sidx[ixj] = ia;
            float fa = sval[tid]; sval[tid] = sval[ixj]; sval[ixj] = fa;
          }
        }
      }
      __syncthreads();
    }
  }

  const int e0 = tid, e1 = tid + 384, e2 = tid + 768;
  float a0 = bdown[e0], a1 = bdown[e1], a2 = bdown[e2];
#pragma unroll 4
  for (int k = 0; k < TOPK; k++) {
    float v = sval[k];
    const float* wr = g_wdt + (size_t)sidx[k] * DEMB;
    a0 = fmaf(v, wr[e0], a0);
    a1 = fmaf(v, wr[e1], a1);
    a2 = fmaf(v, wr[e2], a2);
  }
  float* o = out + (size_t)b * DEMB;
  o[e0] = a0; o[e1] = a1; o[e2] = a2;
}

// ---------------- launch (no device-global ever passed from host) --------------
extern "C" void kernel_launch(void* const* d_in, const int* in_sizes, int n_in,
                              void* d_out, int out_size) {
  const float* embs   = (const float*)d_in[0];
  const float* W_up   = (const float*)d_in[1];
  const float* b_up   = (const float*)d_in[2];
  const float* W_down = (const float*)d_in[3];
  const float* b_down = (const float*)d_in[4];
  float* out = (float*)d_out;

  cvt_A_kernel<<<(BROWS * DEMB) / (256 * 8), 256>>>(embs);
  cvt_W_kernel<<<((size_t)DHID * DEMB) / (256 * 8), 256>>>(W_up);
  transpose_kernel<<<dim3(DHID / 32, DEMB / 32), dim3(32, 8)>>>(W_down);

  gemm_bf16_kernel<<<dim3(BROWS / BM, DHID / BN), 256>>>(b_up);

  select_kernel<<<BROWS, 256>>>();
  exact_kernel<<<BROWS, 256>>>(embs, W_up, b_up);
  decoder_kernel<<<BROWS, 384>>>(b_down, out);
}

// round 10
// speedup vs baseline: 3.6389x; 1.8731x over previous
#include <cuda_runtime.h>
#include <cuda_bf16.h>
#include <cstdint>
#include <cstddef>

#define BROWS 8192
#define DEMB  1152
#define DHID  32768
#define TOPK  64
#define NCAND 256
#define CRANK 160

// GEMM tiling
#define BM 128
#define BN 256
#define BK 64
#define STAGES 3
#define KITERS 18                  // 1152/64
#define LDB 144                    // padded row bytes (128 data + 16) — conflict-free LDSM
#define STAGE_B ((BM + BN) * LDB)  // 55296
#define GEMM_SMEM (STAGES * STAGE_B)  // 165888

// ---------------- scratch (referenced from DEVICE code only) -------------------
static __device__ __nv_bfloat16 g_ab[(size_t)BROWS * DEMB];
static __device__ __nv_bfloat16 g_wb[(size_t)DHID * DEMB];
static __device__ __nv_bfloat16 g_xb[(size_t)BROWS * DHID];   // approx acts
static __device__ float g_wdt[(size_t)DHID * DEMB];           // W_down^T
static __device__ int   g_cand[(size_t)BROWS * NCAND];
static __device__ int   g_ccnt[BROWS];
static __device__ float g_val[BROWS * TOPK];
static __device__ int   g_idx[BROWS * TOPK];

// ---------------- helpers ------------------------------------------------------
__device__ __forceinline__ uint32_t smem_u32(const void* p) {
  uint32_t a;
  asm("{ .reg .u64 t; cvta.to.shared.u64 t, %1; cvt.u32.u64 %0, t; }" : "=r"(a) : "l"(p));
  return a;
}
__device__ __forceinline__ void cp16(uint32_t dst, const void* src) {
  asm volatile("cp.async.cg.shared.global [%0], [%1], 16;" :: "r"(dst), "l"(src));
}
__device__ __forceinline__ void ldsm4(uint32_t* r, uint32_t addr) {
  asm volatile("ldmatrix.sync.aligned.m8n8.x4.shared.b16 {%0,%1,%2,%3}, [%4];"
               : "=r"(r[0]), "=r"(r[1]), "=r"(r[2]), "=r"(r[3]) : "r"(addr) : "memory");
}
__device__ __forceinline__ void mma16816(float* c, const uint32_t* a,
                                         uint32_t b0, uint32_t b1) {
  asm volatile("mma.sync.aligned.m16n8k16.row.col.f32.bf16.bf16.f32 "
               "{%0,%1,%2,%3}, {%4,%5,%6,%7}, {%8,%9}, {%0,%1,%2,%3};"
               : "+f"(c[0]), "+f"(c[1]), "+f"(c[2]), "+f"(c[3])
               : "r"(a[0]), "r"(a[1]), "r"(a[2]), "r"(a[3]), "r"(b0), "r"(b1));
}
__device__ __forceinline__ void cvt8(const float* __restrict__ src,
                                     __nv_bfloat16* __restrict__ dst, size_t i) {
  float4 a = *reinterpret_cast<const float4*>(src + i);
  float4 b = *reinterpret_cast<const float4*>(src + i + 4);
  __nv_bfloat162 p[4];
  p[0] = __float22bfloat162_rn(make_float2(a.x, a.y));
  p[1] = __float22bfloat162_rn(make_float2(a.z, a.w));
  p[2] = __float22bfloat162_rn(make_float2(b.x, b.y));
  p[3] = __float22bfloat162_rn(make_float2(b.z, b.w));
  *reinterpret_cast<uint4*>(dst + i) = *reinterpret_cast<uint4*>(p);
}

// ---------------- kernel 0a/0b: fp32 -> bf16 ------------------------------------
__global__ void cvt_A_kernel(const float* __restrict__ src) {
  size_t i = ((size_t)blockIdx.x * blockDim.x + threadIdx.x) * 8;
  cvt8(src, g_ab, i);
}
__global__ void cvt_W_kernel(const float* __restrict__ src) {
  size_t i = ((size_t)blockIdx.x * blockDim.x + threadIdx.x) * 8;
  cvt8(src, g_wb, i);
}

// ---------------- kernel 1: bf16 mma.sync GEMM, 128x256x64, 3-stage ------------
__device__ __forceinline__ void load_stage(uint32_t sb, int it, int tid,
                                           const __nv_bfloat16* Ag,
                                           const __nv_bfloat16* Bg) {
  if (it < KITERS) {
    uint32_t base = sb + (it % STAGES) * STAGE_B;
    int k0 = it * BK;
    // 384 rows x 8 chunks of 16B; rows [0,128)=A, [128,384)=B; contiguous in smem
#pragma unroll
    for (int j = 0; j < 12; j++) {
      int c = tid + j * 256;
      int row = c >> 3, kc = c & 7;
      const __nv_bfloat16* src = (row < BM)
          ? Ag + (size_t)row * DEMB + k0 + kc * 8
          : Bg + (size_t)(row - BM) * DEMB + k0 + kc * 8;
      cp16(base + row * LDB + kc * 16, src);
    }
  }
  asm volatile("cp.async.commit_group;" ::: "memory");
}

__global__ __launch_bounds__(256) void gemm_bf16_kernel(const float* __restrict__ bias) {
  extern __shared__ __align__(128) char smem[];
  const uint32_t sb = smem_u32(smem);
  const int tid = threadIdx.x, lane = tid & 31, wid = tid >> 5;
  const int bm = blockIdx.x, bn = blockIdx.y;
  const int wm = wid >> 2, wn = wid & 3;   // 2x4 warps, warp tile 64x64

  const __nv_bfloat16* Ag = g_ab + (size_t)bm * BM * DEMB;
  const __nv_bfloat16* Bg = g_wb + (size_t)bn * BN * DEMB;

  float acc[4][8][4];
#pragma unroll
  for (int i = 0; i < 4; i++)
#pragma unroll
    for (int j = 0; j < 8; j++)
#pragma unroll
      for (int q = 0; q < 4; q++) acc[i][j][q] = 0.f;

  load_stage(sb, 0, tid, Ag, Bg);
  load_stage(sb, 1, tid, Ag, Bg);

  const uint32_t rsel = (lane & 15);
  const uint32_t ksel = (lane >> 4) * 16;

  for (int it = 0; it < KITERS; ++it) {
    asm volatile("cp.async.wait_group 1;" ::: "memory");
    __syncthreads();
    const uint32_t Ab = sb + (it % STAGES) * STAGE_B;
    const uint32_t Bb = Ab + BM * LDB;
#pragma unroll
    for (int ks = 0; ks < 4; ++ks) {
      const uint32_t koff = ks * 32 + ksel;
      uint32_t afr[4][4];
#pragma unroll
      for (int mi = 0; mi < 4; mi++)
        ldsm4(afr[mi], Ab + (wm * 64 + mi * 16 + rsel) * LDB + koff);
      uint32_t bfr[4][4];
#pragma unroll
      for (int nj = 0; nj < 4; nj++)
        ldsm4(bfr[nj], Bb + (wn * 64 + nj * 16 + rsel) * LDB + koff);
#pragma unroll
      for (int mi = 0; mi < 4; mi++)
#pragma unroll
        for (int nj = 0; nj < 4; nj++) {
          mma16816(acc[mi][2 * nj],     afr[mi], bfr[nj][0], bfr[nj][2]);
          mma16816(acc[mi][2 * nj + 1], afr[mi], bfr[nj][1], bfr[nj][3]);
        }
    }
    load_stage(sb, it + 2, tid, Ag, Bg);   // slot (it+2)%3 last read at it-1: safe
  }

  // epilogue: bias + relu + bf16 store
  const int mrow0 = bm * BM + wm * 64;
  const int ncol0 = bn * BN + wn * 64;
#pragma unroll
  for (int nn = 0; nn < 8; nn++) {
    const int col = ncol0 + nn * 8 + 2 * (lane & 3);
    const float2 bv = *reinterpret_cast<const float2*>(bias + col);
#pragma unroll
    for (int mi = 0; mi < 4; mi++) {
      const int r0 = mrow0 + mi * 16 + (lane >> 2);
      float v0 = fmaxf(acc[mi][nn][0] + bv.x, 0.f);
      float v1 = fmaxf(acc[mi][nn][1] + bv.y, 0.f);
      float v2 = fmaxf(acc[mi][nn][2] + bv.x, 0.f);
      float v3 = fmaxf(acc[mi][nn][3] + bv.y, 0.f);
      __nv_bfloat162 p0 = __float22bfloat162_rn(make_float2(v0, v1));
      __nv_bfloat162 p1 = __float22bfloat162_rn(make_float2(v2, v3));
      *reinterpret_cast<uint32_t*>(g_xb + (size_t)r0 * DHID + col) =
          *reinterpret_cast<uint32_t*>(&p0);
      *reinterpret_cast<uint32_t*>(g_xb + (size_t)(r0 + 8) * DHID + col) =
          *reinterpret_cast<uint32_t*>(&p1);
    }
  }
}

// ---------------- kernel 2: transpose W_down -----------------------------------
__global__ void transpose_kernel(const float* __restrict__ W) {
  __shared__ float tile[32][33];
  int x = blockIdx.x * 32 + threadIdx.x;
  int y = blockIdx.y * 32 + threadIdx.y;
#pragma unroll
  for (int j = 0; j < 32; j += 8)
    tile[threadIdx.y + j][threadIdx.x] = W[(size_t)(y + j) * DHID + x];
  __syncthreads();
  int xo = blockIdx.y * 32 + threadIdx.x;
  int yo = blockIdx.x * 32 + threadIdx.y;
#pragma unroll
  for (int j = 0; j < 32; j += 8)
    g_wdt[(size_t)(yo + j) * DEMB + xo] = tile[threadIdx.x][threadIdx.y + j];
}

// ---------------- kernel 3: candidate selection (rank-160 of x-hat) ------------
__global__ __launch_bounds__(256) void select_kernel() {
  __shared__ unsigned hist[4096];          // bins = u >> 4
  __shared__ unsigned hist16[16];
  __shared__ int s_c1, s_cc;
  __shared__ unsigned s_binA, s_needA, s_thr;

  const int row = blockIdx.x, tid = threadIdx.x;
  const uint4* xr4 = reinterpret_cast<const uint4*>(g_xb + (size_t)row * DHID);

  for (int i = tid; i < 4096; i += 256) hist[i] = 0;
  if (tid < 16) hist16[tid] = 0;
  if (tid == 0) { s_c1 = 0; s_cc = 0; }
  __syncthreads();

  int c1 = 0;
  for (int i = tid; i < DHID / 8; i += 256) {
    uint4 v = xr4[i];
    unsigned w[4] = {v.x, v.y, v.z, v.w};
#pragma unroll
    for (int q = 0; q < 4; q++) {
      unsigned u0 = w[q] & 0xFFFFu, u1 = w[q] >> 16;
      if (u0 >= 0x3F80u) { atomicAdd(&hist[u0 >> 4], 1u); c1++; }
      if (u1 >= 0x3F80u) { atomicAdd(&hist[u1 >> 4], 1u); c1++; }
    }
  }
#pragma unroll
  for (int o = 16; o; o >>= 1) c1 += __shfl_xor_sync(0xffffffff, c1, o);
  if ((tid & 31) == 0) atomicAdd(&s_c1, c1);
  __syncthreads();

  if (tid == 0) {
    if (s_c1 >= CRANK) {
      unsigned cum = 0;
      for (int b = 4095; b >= 0; b--) {
        unsigned h = hist[b];
        if (cum + h >= CRANK) { s_binA = (unsigned)b; s_needA = CRANK - cum; break; }
        cum += h;
      }
    } else {
      s_binA = 0xFFFFFFFFu;
      s_thr = 1u;
    }
  }
  __syncthreads();
  const unsigned binA = s_binA;

  if (binA != 0xFFFFFFFFu) {
    for (int i = tid; i < DHID / 8; i += 256) {
      uint4 v = xr4[i];
      unsigned w[4] = {v.x, v.y, v.z, v.w};
#pragma unroll
      for (int q = 0; q < 4; q++) {
        unsigned u0 = w[q] & 0xFFFFu, u1 = w[q] >> 16;
        if ((u0 >> 4) == binA) atomicAdd(&hist16[u0 & 15u], 1u);
        if ((u1 >> 4) == binA) atomicAdd(&hist16[u1 & 15u], 1u);
      }
    }
    __syncthreads();
    if (tid == 0) {
      unsigned cum = 0, need = s_needA;
      unsigned thr = binA << 4;
      for (int b = 15; b >= 0; b--) {
        unsigned h = hist16[b];
        if (cum + h >= need) { thr = (binA << 4) | (unsigned)b; break; }
        cum += h;
      }
      s_thr = thr;
    }
    __syncthreads();
  }
  const unsigned thr = s_thr;

  for (int i = tid; i < DHID / 8; i += 256) {
    uint4 v = xr4[i];
    unsigned w[4] = {v.x, v.y, v.z, v.w};
#pragma unroll
    for (int q = 0; q < 4; q++) {
      unsigned u0 = w[q] & 0xFFFFu, u1 = w[q] >> 16;
      if (u0 >= thr && u0 != 0) {
        int p = atomicAdd(&s_cc, 1);
        if (p < NCAND) g_cand[(size_t)row * NCAND + p] = i * 8 + q * 2;
      }
      if (u1 >= thr && u1 != 0) {
        int p = atomicAdd(&s_cc, 1);
        if (p < NCAND) g_cand[(size_t)row * NCAND + p] = i * 8 + q * 2 + 1;
      }
    }
  }
  __syncthreads();
  if (tid == 0) g_ccnt[row] = (s_cc < NCAND) ? s_cc : NCAND;
}

// ---------------- kernel 4: R1-identical fp32 rescore + exact top-64 -----------
// One thread per candidate; strictly sequential k-ascending fmaf chain (bit-
// identical to the R1/R9 arithmetic that matches the reference on sub-ulp ties).
// float4 loads preserve the exact fma order.
__global__ __launch_bounds__(256) void exact_kernel(const float* __restrict__ embs,
                                                    const float* __restrict__ W,
                                                    const float* __restrict__ bup) {
  __shared__ float ar[DEMB];
  __shared__ float sval[NCAND];
  __shared__ int   sidx[NCAND];
  const int row = blockIdx.x, tid = threadIdx.x;

  for (int i = tid; i < DEMB; i += 256) ar[i] = embs[(size_t)row * DEMB + i];
  sval[tid] = -1e30f;
  sidx[tid] = 0;
  __syncthreads();

  const int cnt = g_ccnt[row];
  if (tid < cnt) {
    const int h = g_cand[(size_t)row * NCAND + tid];
    const float4* wr4 = reinterpret_cast<const float4*>(W + (size_t)h * DEMB);
    float acc = 0.f;
#pragma unroll 4
    for (int kk = 0; kk < DEMB / 4; kk++) {
      float4 w = __ldg(wr4 + kk);
      const int k = kk * 4;
      acc = __fmaf_rn(ar[k + 0], w.x, acc);
      acc = __fmaf_rn(ar[k + 1], w.y, acc);
      acc = __fmaf_rn(ar[k + 2], w.z, acc);
      acc = __fmaf_rn(ar[k + 3], w.w, acc);
    }
    sval[tid] = fmaxf(acc + __ldg(bup + h), 0.f);
    sidx[tid] = h;
  }
  __syncthreads();

  for (int k = 2; k <= NCAND; k <<= 1) {
    for (int j = k >> 1; j > 0; j >>= 1) {
      int ixj = tid ^ j;
      if (ixj > tid) {
        bool up = ((tid & k) == 0);
        float va = sval[tid], vb = sval[ixj];
        bool sw = up ? (va > vb) : (va < vb);
        if (sw) {
          sval[tid] = vb; sval[ixj] = va;
          int t = sidx[tid]; sidx[tid] = sidx[ixj]; sidx[ixj] = t;
        }
      }
      __syncthreads();
    }
  }

  float thr = sval[191];
  if (tid >= 192) {
    int j = tid - 192;
    bool keep = sval[tid] > thr;
    g_val[row * TOPK + j] = keep ? sval[tid] : 0.f;
    g_idx[row * TOPK + j] = keep ? sidx[tid] : 0;
  }
}

// ---------------- kernel 5: sparse decoder -------------------------------------
__global__ __launch_bounds__(384) void decoder_kernel(
    const float* __restrict__ bdown, float* __restrict__ out) {
  const int b = blockIdx.x;
  const int tid = threadIdx.x;
  __shared__ int   sidx[TOPK];
  __shared__ float sval[TOPK];
  if (tid < TOPK) {
    sidx[tid] = g_idx[b * TOPK + tid];
    sval[tid] = g_val[b * TOPK + tid];
  }
  __syncthreads();

  for (int k = 2; k <= TOPK; k <<= 1) {
    for (int j = k >> 1; j > 0; j >>= 1) {
      if (tid < TOPK) {
        int ixj = tid ^ j;
        if (ixj > tid) {
          bool up = ((tid & k) == 0);
          int ia = sidx[tid], ib = sidx[ixj];
          bool sw = up ? (ia > ib) : (ia < ib);
          if (sw) {
            sidx[tid] = ib; sidx[ixj] = ia;
            float fa = sval[tid]; sval[tid] = sval[ixj]; sval[ixj] = fa;
          }
        }
      }
      __syncthreads();
    }
  }

  const int e0 = tid, e1 = tid + 384, e2 = tid + 768;
  float a0 = bdown[e0], a1 = bdown[e1], a2 = bdown[e2];
#pragma unroll 4
  for (int k = 0; k < TOPK; k++) {
    float v = sval[k];
    const float* wr = g_wdt + (size_t)sidx[k] * DEMB;
    a0 = fmaf(v, wr[e0], a0);
    a1 = fmaf(v, wr[e1], a1);
    a2 = fmaf(v, wr[e2], a2);
  }
  float* o = out + (size_t)b * DEMB;
  o[e0] = a0; o[e1] = a1; o[e2] = a2;
}

// ---------------- launch -------------------------------------------------------
extern "C" void kernel_launch(void* const* d_in, const int* in_sizes, int n_in,
                              void* d_out, int out_size) {
  const float* embs   = (const float*)d_in[0];
  const float* W_up   = (const float*)d_in[1];
  const float* b_up   = (const float*)d_in[2];
  const float* W_down = (const float*)d_in[3];
  const float* b_down = (const float*)d_in[4];
  float* out = (float*)d_out;

  cudaFuncSetAttribute(gemm_bf16_kernel,
                       cudaFuncAttributeMaxDynamicSharedMemorySize, GEMM_SMEM);

  cvt_A_kernel<<<(BROWS * DEMB) / (256 * 8), 256>>>(embs);
  cvt_W_kernel<<<((size_t)DHID * DEMB) / (256 * 8), 256>>>(W_up);
  transpose_kernel<<<dim3(DHID / 32, DEMB / 32), dim3(32, 8)>>>(W_down);

  gemm_bf16_kernel<<<dim3(BROWS / BM, DHID / BN), 256, GEMM_SMEM>>>(b_up);

  select_kernel<<<BROWS, 256>>>();
  exact_kernel<<<BROWS, 256>>>(embs, W_up, b_up);
  decoder_kernel<<<BROWS, 384>>>(b_down, out);
}

// round 11
// speedup vs baseline: 3.7027x; 1.0175x over previous
#include <cuda_runtime.h>
#include <cuda_bf16.h>
#include <cstdint>
#include <cstddef>

#define BROWS 8192
#define DEMB  1152
#define DHID  32768
#define TOPK  64
#define NCAND 256
#define CRANK 160

// GEMM tiling
#define BM 128
#define BN 256
#define BK 64
#define STAGES 3
#define KITERS 18                  // 1152/64
#define LDB 144                    // padded row bytes (128 data + 16) — conflict-free LDSM
#define STAGE_B ((BM + BN) * LDB)  // 55296
#define GEMM_SMEM (STAGES * STAGE_B)  // 165888
#define GTHREADS 512

// ---------------- scratch (referenced from DEVICE code only) -------------------
static __device__ __nv_bfloat16 g_ab[(size_t)BROWS * DEMB];
static __device__ __nv_bfloat16 g_wb[(size_t)DHID * DEMB];
static __device__ __nv_bfloat16 g_xb[(size_t)BROWS * DHID];   // approx acts
static __device__ float g_wdt[(size_t)DHID * DEMB];           // W_down^T
static __device__ int   g_cand[(size_t)BROWS * NCAND];
static __device__ int   g_ccnt[BROWS];
static __device__ float g_val[BROWS * TOPK];
static __device__ int   g_idx[BROWS * TOPK];

// ---------------- helpers ------------------------------------------------------
__device__ __forceinline__ uint32_t smem_u32(const void* p) {
  uint32_t a;
  asm("{ .reg .u64 t; cvta.to.shared.u64 t, %1; cvt.u32.u64 %0, t; }" : "=r"(a) : "l"(p));
  return a;
}
__device__ __forceinline__ void cp16(uint32_t dst, const void* src) {
  asm volatile("cp.async.cg.shared.global [%0], [%1], 16;" :: "r"(dst), "l"(src));
}
__device__ __forceinline__ void ldsm4(uint32_t* r, uint32_t addr) {
  asm volatile("ldmatrix.sync.aligned.m8n8.x4.shared.b16 {%0,%1,%2,%3}, [%4];"
               : "=r"(r[0]), "=r"(r[1]), "=r"(r[2]), "=r"(r[3]) : "r"(addr) : "memory");
}
__device__ __forceinline__ void mma16816(float* c, const uint32_t* a,
                                         uint32_t b0, uint32_t b1) {
  asm volatile("mma.sync.aligned.m16n8k16.row.col.f32.bf16.bf16.f32 "
               "{%0,%1,%2,%3}, {%4,%5,%6,%7}, {%8,%9}, {%0,%1,%2,%3};"
               : "+f"(c[0]), "+f"(c[1]), "+f"(c[2]), "+f"(c[3])
               : "r"(a[0]), "r"(a[1]), "r"(a[2]), "r"(a[3]), "r"(b0), "r"(b1));
}
__device__ __forceinline__ void cvt8(const float* __restrict__ src,
                                     __nv_bfloat16* __restrict__ dst, size_t i) {
  float4 a = *reinterpret_cast<const float4*>(src + i);
  float4 b = *reinterpret_cast<const float4*>(src + i + 4);
  __nv_bfloat162 p[4];
  p[0] = __float22bfloat162_rn(make_float2(a.x, a.y));
  p[1] = __float22bfloat162_rn(make_float2(a.z, a.w));
  p[2] = __float22bfloat162_rn(make_float2(b.x, b.y));
  p[3] = __float22bfloat162_rn(make_float2(b.z, b.w));
  *reinterpret_cast<uint4*>(dst + i) = *reinterpret_cast<uint4*>(p);
}

// ---------------- kernel 0a/0b: fp32 -> bf16 ------------------------------------
__global__ void cvt_A_kernel(const float* __restrict__ src) {
  size_t i = ((size_t)blockIdx.x * blockDim.x + threadIdx.x) * 8;
  cvt8(src, g_ab, i);
}
__global__ void cvt_W_kernel(const float* __restrict__ src) {
  size_t i = ((size_t)blockIdx.x * blockDim.x + threadIdx.x) * 8;
  cvt8(src, g_wb, i);
}

// ---------------- kernel 1: bf16 mma.sync GEMM, 128x256x64, 3-stage, 16 warps --
__device__ __forceinline__ void load_stage(uint32_t sb, int it, int tid,
                                           const __nv_bfloat16* Ag,
                                           const __nv_bfloat16* Bg) {
  if (it < KITERS) {
    uint32_t base = sb + (it % STAGES) * STAGE_B;
    int k0 = it * BK;
    // 384 rows x 8 chunks of 16B; rows [0,128)=A, [128,384)=B
#pragma unroll
    for (int j = 0; j < 6; j++) {
      int c = tid + j * GTHREADS;
      int row = c >> 3, kc = c & 7;
      const __nv_bfloat16* src = (row < BM)
          ? Ag + (size_t)row * DEMB + k0 + kc * 8
          : Bg + (size_t)(row - BM) * DEMB + k0 + kc * 8;
      cp16(base + row * LDB + kc * 16, src);
    }
  }
  asm volatile("cp.async.commit_group;" ::: "memory");
}

__global__ __launch_bounds__(GTHREADS) void gemm_bf16_kernel(const float* __restrict__ bias) {
  extern __shared__ __align__(128) char smem[];
  const uint32_t sb = smem_u32(smem);
  const int tid = threadIdx.x, lane = tid & 31, wid = tid >> 5;
  const int bm = blockIdx.x, bn = blockIdx.y;
  const int wm = wid >> 2, wn = wid & 3;   // 4x4 warps, warp tile 32x64

  const __nv_bfloat16* Ag = g_ab + (size_t)bm * BM * DEMB;
  const __nv_bfloat16* Bg = g_wb + (size_t)bn * BN * DEMB;

  float acc[2][8][4];
#pragma unroll
  for (int i = 0; i < 2; i++)
#pragma unroll
    for (int j = 0; j < 8; j++)
#pragma unroll
      for (int q = 0; q < 4; q++) acc[i][j][q] = 0.f;

  load_stage(sb, 0, tid, Ag, Bg);
  load_stage(sb, 1, tid, Ag, Bg);

  const uint32_t rsel = (lane & 15);
  const uint32_t ksel = (lane >> 4) * 16;

  for (int it = 0; it < KITERS; ++it) {
    asm volatile("cp.async.wait_group 1;" ::: "memory");
    __syncthreads();
    const uint32_t Ab = sb + (it % STAGES) * STAGE_B;
    const uint32_t Bb = Ab + BM * LDB;
#pragma unroll
    for (int ks = 0; ks < 4; ++ks) {
      const uint32_t koff = ks * 32 + ksel;
      uint32_t afr[2][4];
#pragma unroll
      for (int mi = 0; mi < 2; mi++)
        ldsm4(afr[mi], Ab + (wm * 32 + mi * 16 + rsel) * LDB + koff);
      uint32_t bfr[4][4];
#pragma unroll
      for (int nj = 0; nj < 4; nj++)
        ldsm4(bfr[nj], Bb + (wn * 64 + nj * 16 + rsel) * LDB + koff);
#pragma unroll
      for (int mi = 0; mi < 2; mi++)
#pragma unroll
        for (int nj = 0; nj < 4; nj++) {
          mma16816(acc[mi][2 * nj],     afr[mi], bfr[nj][0], bfr[nj][2]);
          mma16816(acc[mi][2 * nj + 1], afr[mi], bfr[nj][1], bfr[nj][3]);
        }
    }
    load_stage(sb, it + 2, tid, Ag, Bg);   // slot (it+2)%3 last read at it-1: safe
  }

  // epilogue: bias + relu + bf16 store
  const int mrow0 = bm * BM + wm * 32;
  const int ncol0 = bn * BN + wn * 64;
#pragma unroll
  for (int nn = 0; nn < 8; nn++) {
    const int col = ncol0 + nn * 8 + 2 * (lane & 3);
    const float2 bv = *reinterpret_cast<const float2*>(bias + col);
#pragma unroll
    for (int mi = 0; mi < 2; mi++) {
      const int r0 = mrow0 + mi * 16 + (lane >> 2);
      float v0 = fmaxf(acc[mi][nn][0] + bv.x, 0.f);
      float v1 = fmaxf(acc[mi][nn][1] + bv.y, 0.f);
      float v2 = fmaxf(acc[mi][nn][2] + bv.x, 0.f);
      float v3 = fmaxf(acc[mi][nn][3] + bv.y, 0.f);
      __nv_bfloat162 p0 = __float22bfloat162_rn(make_float2(v0, v1));
      __nv_bfloat162 p1 = __float22bfloat162_rn(make_float2(v2, v3));
      *reinterpret_cast<uint32_t*>(g_xb + (size_t)r0 * DHID + col) =
          *reinterpret_cast<uint32_t*>(&p0);
      *reinterpret_cast<uint32_t*>(g_xb + (size_t)(r0 + 8) * DHID + col) =
          *reinterpret_cast<uint32_t*>(&p1);
    }
  }
}

// ---------------- kernel 2: transpose W_down -----------------------------------
__global__ void transpose_kernel(const float* __restrict__ W) {
  __shared__ float tile[32][33];
  int x = blockIdx.x * 32 + threadIdx.x;
  int y = blockIdx.y * 32 + threadIdx.y;
#pragma unroll
  for (int j = 0; j < 32; j += 8)
    tile[threadIdx.y + j][threadIdx.x] = W[(size_t)(y + j) * DHID + x];
  __syncthreads();
  int xo = blockIdx.y * 32 + threadIdx.x;
  int yo = blockIdx.x * 32 + threadIdx.y;
#pragma unroll
  for (int j = 0; j < 32; j += 8)
    g_wdt[(size_t)(yo + j) * DEMB + xo] = tile[threadIdx.x][threadIdx.y + j];
}

// ---------------- kernel 3: candidate selection (rank-160 of x-hat) ------------
__global__ __launch_bounds__(256) void select_kernel() {
  __shared__ unsigned hist[4096];          // bins = u >> 4
  __shared__ unsigned hist16[16];
  __shared__ int s_c1, s_cc;
  __shared__ unsigned s_binA, s_needA, s_thr;

  const int row = blockIdx.x, tid = threadIdx.x;
  const uint4* xr4 = reinterpret_cast<const uint4*>(g_xb + (size_t)row * DHID);

  for (int i = tid; i < 4096; i += 256) hist[i] = 0;
  if (tid < 16) hist16[tid] = 0;
  if (tid == 0) { s_c1 = 0; s_cc = 0; }
  __syncthreads();

  int c1 = 0;
  for (int i = tid; i < DHID / 8; i += 256) {
    uint4 v = xr4[i];
    unsigned w[4] = {v.x, v.y, v.z, v.w};
#pragma unroll
    for (int q = 0; q < 4; q++) {
      unsigned u0 = w[q] & 0xFFFFu, u1 = w[q] >> 16;
      if (u0 >= 0x3F80u) { atomicAdd(&hist[u0 >> 4], 1u); c1++; }
      if (u1 >= 0x3F80u) { atomicAdd(&hist[u1 >> 4], 1u); c1++; }
    }
  }
#pragma unroll
  for (int o = 16; o; o >>= 1) c1 += __shfl_xor_sync(0xffffffff, c1, o);
  if ((tid & 31) == 0) atomicAdd(&s_c1, c1);
  __syncthreads();

  if (tid == 0) {
    if (s_c1 >= CRANK) {
      unsigned cum = 0;
      for (int b = 4095; b >= 0; b--) {
        unsigned h = hist[b];
        if (cum + h >= CRANK) { s_binA = (unsigned)b; s_needA = CRANK - cum; break; }
        cum += h;
      }
    } else {
      s_binA = 0xFFFFFFFFu;
      s_thr = 1u;
    }
  }
  __syncthreads();
  const unsigned binA = s_binA;

  if (binA != 0xFFFFFFFFu) {
    for (int i = tid; i < DHID / 8; i += 256) {
      uint4 v = xr4[i];
      unsigned w[4] = {v.x, v.y, v.z, v.w};
#pragma unroll
      for (int q = 0; q < 4; q++) {
        unsigned u0 = w[q] & 0xFFFFu, u1 = w[q] >> 16;
        if ((u0 >> 4) == binA) atomicAdd(&hist16[u0 & 15u], 1u);
        if ((u1 >> 4) == binA) atomicAdd(&hist16[u1 & 15u], 1u);
      }
    }
    __syncthreads();
    if (tid == 0) {
      unsigned cum = 0, need = s_needA;
      unsigned thr = binA << 4;
      for (int b = 15; b >= 0; b--) {
        unsigned h = hist16[b];
        if (cum + h >= need) { thr = (binA << 4) | (unsigned)b; break; }
        cum += h;
      }
      s_thr = thr;
    }
    __syncthreads();
  }
  const unsigned thr = s_thr;

  for (int i = tid; i < DHID / 8; i += 256) {
    uint4 v = xr4[i];
    unsigned w[4] = {v.x, v.y, v.z, v.w};
#pragma unroll
    for (int q = 0; q < 4; q++) {
      unsigned u0 = w[q] & 0xFFFFu, u1 = w[q] >> 16;
      if (u0 >= thr && u0 != 0) {
        int p = atomicAdd(&s_cc, 1);
        if (p < NCAND) g_cand[(size_t)row * NCAND + p] = i * 8 + q * 2;
      }
      if (u1 >= thr && u1 != 0) {
        int p = atomicAdd(&s_cc, 1);
        if (p < NCAND) g_cand[(size_t)row * NCAND + p] = i * 8 + q * 2 + 1;
      }
    }
  }
  __syncthreads();
  if (tid == 0) g_ccnt[row] = (s_cc < NCAND) ? s_cc : NCAND;
}

// ---------------- kernel 4: R1-identical fp32 rescore + exact top-64 -----------
__global__ __launch_bounds__(256) void exact_kernel(const float* __restrict__ embs,
                                                    const float* __restrict__ W,
                                                    const float* __restrict__ bup) {
  __shared__ float ar[DEMB];
  __shared__ float sval[NCAND];
  __shared__ int   sidx[NCAND];
  const int row = blockIdx.x, tid = threadIdx.x;

  for (int i = tid; i < DEMB; i += 256) ar[i] = embs[(size_t)row * DEMB + i];
  sval[tid] = -1e30f;
  sidx[tid] = 0;
  __syncthreads();

  const int cnt = g_ccnt[row];
  if (tid < cnt) {
    const int h = g_cand[(size_t)row * NCAND + tid];
    const float4* wr4 = reinterpret_cast<const float4*>(W + (size_t)h * DEMB);
    float acc = 0.f;
#pragma unroll 4
    for (int kk = 0; kk < DEMB / 4; kk++) {
      float4 w = __ldg(wr4 + kk);
      const int k = kk * 4;
      acc = __fmaf_rn(ar[k + 0], w.x, acc);
      acc = __fmaf_rn(ar[k + 1], w.y, acc);
      acc = __fmaf_rn(ar[k + 2], w.z, acc);
      acc = __fmaf_rn(ar[k + 3], w.w, acc);
    }
    sval[tid] = fmaxf(acc + __ldg(bup + h), 0.f);
    sidx[tid] = h;
  }
  __syncthreads();

  for (int k = 2; k <= NCAND; k <<= 1) {
    for (int j = k >> 1; j > 0; j >>= 1) {
      int ixj = tid ^ j;
      if (ixj > tid) {
        bool up = ((tid & k) == 0);
        float va = sval[tid], vb = sval[ixj];
        bool sw = up ? (va > vb) : (va < vb);
        if (sw) {
          sval[tid] = vb; sval[ixj] = va;
          int t = sidx[tid]; sidx[tid] = sidx[ixj]; sidx[ixj] = t;
        }
      }
      __syncthreads();
    }
  }

  float thr = sval[191];
  if (tid >= 192) {
    int j = tid - 192;
    bool keep = sval[tid] > thr;
    g_val[row * TOPK + j] = keep ? sval[tid] : 0.f;
    g_idx[row * TOPK + j] = keep ? sidx[tid] : 0;
  }
}

// ---------------- kernel 5: sparse decoder -------------------------------------
__global__ __launch_bounds__(384) void decoder_kernel(
    const float* __restrict__ bdown, float* __restrict__ out) {
  const int b = blockIdx.x;
  const int tid = threadIdx.x;
  __shared__ int   sidx[TOPK];
  __shared__ float sval[TOPK];
  if (tid < TOPK) {
    sidx[tid] = g_idx[b * TOPK + tid];
    sval[tid] = g_val[b * TOPK + tid];
  }
  __syncthreads();

  for (int k = 2; k <= TOPK; k <<= 1) {
    for (int j = k >> 1; j > 0; j >>= 1) {
      if (tid < TOPK) {
        int ixj = tid ^ j;
        if (ixj > tid) {
          bool up = ((tid & k) == 0);
          int ia = sidx[tid], ib = sidx[ixj];
          bool sw = up ? (ia > ib) : (ia < ib);
          if (sw) {
            sidx[tid] = ib; sidx[ixj] = ia;
            float fa = sval[tid]; sval[tid] = sval[ixj]; sval[ixj] = fa;
          }
        }
      }
      __syncthreads();
    }
  }

  const int e0 = tid, e1 = tid + 384, e2 = tid + 768;
  float a0 = bdown[e0], a1 = bdown[e1], a2 = bdown[e2];
#pragma unroll 4
  for (int k = 0; k < TOPK; k++) {
    float v = sval[k];
    const float* wr = g_wdt + (size_t)sidx[k] * DEMB;
    a0 = fmaf(v, wr[e0], a0);
    a1 = fmaf(v, wr[e1], a1);
    a2 = fmaf(v, wr[e2], a2);
  }
  float* o = out + (size_t)b * DEMB;
  o[e0] = a0; o[e1] = a1; o[e2] = a2;
}

// ---------------- launch -------------------------------------------------------
extern "C" void kernel_launch(void* const* d_in, const int* in_sizes, int n_in,
                              void* d_out, int out_size) {
  const float* embs   = (const float*)d_in[0];
  const float* W_up   = (const float*)d_in[1];
  const float* b_up   = (const float*)d_in[2];
  const float* W_down = (const float*)d_in[3];
  const float* b_down = (const float*)d_in[4];
  float* out = (float*)d_out;

  cudaFuncSetAttribute(gemm_bf16_kernel,
                       cudaFuncAttributeMaxDynamicSharedMemorySize, GEMM_SMEM);

  cvt_A_kernel<<<(BROWS * DEMB) / (256 * 8), 256>>>(embs);
  cvt_W_kernel<<<((size_t)DHID * DEMB) / (256 * 8), 256>>>(W_up);
  transpose_kernel<<<dim3(DHID / 32, DEMB / 32), dim3(32, 8)>>>(W_down);

  gemm_bf16_kernel<<<dim3(BROWS / BM, DHID / BN), GTHREADS, GEMM_SMEM>>>(b_up);

  select_kernel<<<BROWS, 256>>>();
  exact_kernel<<<BROWS, 256>>>(embs, W_up, b_up);
  decoder_kernel<<<BROWS, 384>>>(b_down, out);
}

// round 12
// speedup vs baseline: 3.8380x; 1.0365x over previous
#include <cuda_runtime.h>
#include <cuda_bf16.h>
#include <cstdint>
#include <cstddef>

#define BROWS 8192
#define DEMB  1152
#define DHID  32768
#define TOPK  64
#define NCAND 256
#define CRANK 160

// GEMM tiling — 2 CTAs/SM
#define BM 128
#define BN 128
#define BK 64
#define STAGES 3
#define KITERS 18                  // 1152/64
#define LDB 144                    // padded row bytes (128 data + 16) — conflict-free LDSM
#define STAGE_B ((BM + BN) * LDB)  // 36864
#define GEMM_SMEM (STAGES * STAGE_B)  // 110592 -> 2 CTAs (221K < 228K)
#define GTHREADS 256

// ---------------- scratch (referenced from DEVICE code only) -------------------
static __device__ __nv_bfloat16 g_ab[(size_t)BROWS * DEMB];
static __device__ __nv_bfloat16 g_wb[(size_t)DHID * DEMB];
static __device__ __nv_bfloat16 g_xb[(size_t)BROWS * DHID];   // approx acts
static __device__ float g_wdt[(size_t)DHID * DEMB];           // W_down^T
static __device__ int   g_cand[(size_t)BROWS * NCAND];
static __device__ int   g_ccnt[BROWS];
static __device__ float g_val[BROWS * TOPK];
static __device__ int   g_idx[BROWS * TOPK];

// ---------------- helpers ------------------------------------------------------
__device__ __forceinline__ uint32_t smem_u32(const void* p) {
  uint32_t a;
  asm("{ .reg .u64 t; cvta.to.shared.u64 t, %1; cvt.u32.u64 %0, t; }" : "=r"(a) : "l"(p));
  return a;
}
__device__ __forceinline__ void cp16(uint32_t dst, const void* src) {
  asm volatile("cp.async.cg.shared.global [%0], [%1], 16;" :: "r"(dst), "l"(src));
}
__device__ __forceinline__ void ldsm4(uint32_t* r, uint32_t addr) {
  asm volatile("ldmatrix.sync.aligned.m8n8.x4.shared.b16 {%0,%1,%2,%3}, [%4];"
               : "=r"(r[0]), "=r"(r[1]), "=r"(r[2]), "=r"(r[3]) : "r"(addr) : "memory");
}
__device__ __forceinline__ void mma16816(float* c, const uint32_t* a,
                                         uint32_t b0, uint32_t b1) {
  asm volatile("mma.sync.aligned.m16n8k16.row.col.f32.bf16.bf16.f32 "
               "{%0,%1,%2,%3}, {%4,%5,%6,%7}, {%8,%9}, {%0,%1,%2,%3};"
               : "+f"(c[0]), "+f"(c[1]), "+f"(c[2]), "+f"(c[3])
               : "r"(a[0]), "r"(a[1]), "r"(a[2]), "r"(a[3]), "r"(b0), "r"(b1));
}
__device__ __forceinline__ void cvt8(const float* __restrict__ src,
                                     __nv_bfloat16* __restrict__ dst, size_t i) {
  float4 a = *reinterpret_cast<const float4*>(src + i);
  float4 b = *reinterpret_cast<const float4*>(src + i + 4);
  __nv_bfloat162 p[4];
  p[0] = __float22bfloat162_rn(make_float2(a.x, a.y));
  p[1] = __float22bfloat162_rn(make_float2(a.z, a.w));
  p[2] = __float22bfloat162_rn(make_float2(b.x, b.y));
  p[3] = __float22bfloat162_rn(make_float2(b.z, b.w));
  *reinterpret_cast<uint4*>(dst + i) = *reinterpret_cast<uint4*>(p);
}

// ---------------- kernel 0a/0b: fp32 -> bf16 ------------------------------------
__global__ void cvt_A_kernel(const float* __restrict__ src) {
  size_t i = ((size_t)blockIdx.x * blockDim.x + threadIdx.x) * 8;
  cvt8(src, g_ab, i);
}
__global__ void cvt_W_kernel(const float* __restrict__ src) {
  size_t i = ((size_t)blockIdx.x * blockDim.x + threadIdx.x) * 8;
  cvt8(src, g_wb, i);
}

// ---------------- kernel 1: bf16 mma.sync GEMM, 128x128x64, 3-stage, 2 CTA/SM --
__global__ __launch_bounds__(GTHREADS, 2) void gemm_bf16_kernel(const float* __restrict__ bias) {
  extern __shared__ __align__(128) char smem[];
  const uint32_t sb = smem_u32(smem);
  const int tid = threadIdx.x, lane = tid & 31, wid = tid >> 5;
  const int bm = blockIdx.x, bn = blockIdx.y;
  const int wm = wid >> 1, wn = wid & 1;   // 4x2 warps, warp tile 32x64

  // loader: per-thread fixed src pointers + smem offsets (pointer-stride form)
  const int lrow = tid >> 3, lkc = tid & 7;
  const __nv_bfloat16* srcA = g_ab + (size_t)(bm * BM + lrow) * DEMB + lkc * 8;
  const __nv_bfloat16* srcB = g_wb + (size_t)(bn * BN + lrow) * DEMB + lkc * 8;
  const uint32_t dstoff = lrow * LDB + lkc * 16;

  float acc[2][8][4];
#pragma unroll
  for (int i = 0; i < 2; i++)
#pragma unroll
    for (int j = 0; j < 8; j++)
#pragma unroll
      for (int q = 0; q < 4; q++) acc[i][j][q] = 0.f;

#define LOAD_STAGE(IT)                                                      \
  do {                                                                      \
    int _it = (IT);                                                         \
    if (_it < KITERS) {                                                     \
      uint32_t abase = sb + (_it % STAGES) * STAGE_B + dstoff;              \
      uint32_t bbase = abase + BM * LDB;                                    \
      const __nv_bfloat16* sa = srcA + _it * BK;                            \
      const __nv_bfloat16* sbp = srcB + _it * BK;                           \
      _Pragma("unroll")                                                     \
      for (int j = 0; j < 4; j++) {                                         \
        cp16(abase + j * (32 * LDB), sa + (size_t)j * 32 * DEMB);           \
        cp16(bbase + j * (32 * LDB), sbp + (size_t)j * 32 * DEMB);          \
      }                                                                     \
    }                                                                       \
    asm volatile("cp.async.commit_group;" ::: "memory");                    \
  } while (0)

  LOAD_STAGE(0);
  LOAD_STAGE(1);

  const uint32_t rsel = (lane & 15);
  const uint32_t ksel = (lane >> 4) * 16;

  for (int it = 0; it < KITERS; ++it) {
    asm volatile("cp.async.wait_group 1;" ::: "memory");
    __syncthreads();
    const uint32_t Ab = sb + (it % STAGES) * STAGE_B;
    const uint32_t Bb = Ab + BM * LDB;
#pragma unroll
    for (int ks = 0; ks < 4; ++ks) {
      const uint32_t koff = ks * 32 + ksel;
      uint32_t afr[2][4];
#pragma unroll
      for (int mi = 0; mi < 2; mi++)
        ldsm4(afr[mi], Ab + (wm * 32 + mi * 16 + rsel) * LDB + koff);
      uint32_t bfr[4][4];
#pragma unroll
      for (int nj = 0; nj < 4; nj++)
        ldsm4(bfr[nj], Bb + (wn * 64 + nj * 16 + rsel) * LDB + koff);
#pragma unroll
      for (int mi = 0; mi < 2; mi++)
#pragma unroll
        for (int nj = 0; nj < 4; nj++) {
          mma16816(acc[mi][2 * nj],     afr[mi], bfr[nj][0], bfr[nj][2]);
          mma16816(acc[mi][2 * nj + 1], afr[mi], bfr[nj][1], bfr[nj][3]);
        }
    }
    LOAD_STAGE(it + 2);   // slot (it+2)%3 last read at it-1: safe, no 2nd barrier
  }

  // epilogue: bias + relu + bf16 store
  const int mrow0 = bm * BM + wm * 32;
  const int ncol0 = bn * BN + wn * 64;
#pragma unroll
  for (int nn = 0; nn < 8; nn++) {
    const int col = ncol0 + nn * 8 + 2 * (lane & 3);
    const float2 bv = *reinterpret_cast<const float2*>(bias + col);
#pragma unroll
    for (int mi = 0; mi < 2; mi++) {
      const int r0 = mrow0 + mi * 16 + (lane >> 2);
      float v0 = fmaxf(acc[mi][nn][0] + bv.x, 0.f);
      float v1 = fmaxf(acc[mi][nn][1] + bv.y, 0.f);
      float v2 = fmaxf(acc[mi][nn][2] + bv.x, 0.f);
      float v3 = fmaxf(acc[mi][nn][3] + bv.y, 0.f);
      __nv_bfloat162 p0 = __float22bfloat162_rn(make_float2(v0, v1));
      __nv_bfloat162 p1 = __float22bfloat162_rn(make_float2(v2, v3));
      *reinterpret_cast<uint32_t*>(g_xb + (size_t)r0 * DHID + col) =
          *reinterpret_cast<uint32_t*>(&p0);
      *reinterpret_cast<uint32_t*>(g_xb + (size_t)(r0 + 8) * DHID + col) =
          *reinterpret_cast<uint32_t*>(&p1);
    }
  }
}

// ---------------- kernel 2: transpose W_down -----------------------------------
__global__ void transpose_kernel(const float* __restrict__ W) {
  __shared__ float tile[32][33];
  int x = blockIdx.x * 32 + threadIdx.x;
  int y = blockIdx.y * 32 + threadIdx.y;
#pragma unroll
  for (int j = 0; j < 32; j += 8)
    tile[threadIdx.y + j][threadIdx.x] = W[(size_t)(y + j) * DHID + x];
  __syncthreads();
  int xo = blockIdx.y * 32 + threadIdx.x;
  int yo = blockIdx.x * 32 + threadIdx.y;
#pragma unroll
  for (int j = 0; j < 32; j += 8)
    g_wdt[(size_t)(yo + j) * DEMB + xo] = tile[threadIdx.x][threadIdx.y + j];
}

// ---------------- kernel 3: candidate selection (rank-160 of x-hat) ------------
__global__ __launch_bounds__(256) void select_kernel() {
  __shared__ unsigned hist[4096];          // bins = u >> 4
  __shared__ unsigned hist16[16];
  __shared__ int s_c1, s_cc;
  __shared__ unsigned s_binA, s_needA, s_thr;

  const int row = blockIdx.x, tid = threadIdx.x;
  const uint4* xr4 = reinterpret_cast<const uint4*>(g_xb + (size_t)row * DHID);

  for (int i = tid; i < 4096; i += 256) hist[i] = 0;
  if (tid < 16) hist16[tid] = 0;
  if (tid == 0) { s_c1 = 0; s_cc = 0; }
  __syncthreads();

  int c1 = 0;
  for (int i = tid; i < DHID / 8; i += 256) {
    uint4 v = xr4[i];
    unsigned w[4] = {v.x, v.y, v.z, v.w};
#pragma unroll
    for (int q = 0; q < 4; q++) {
      unsigned u0 = w[q] & 0xFFFFu, u1 = w[q] >> 16;
      if (u0 >= 0x3F80u) { atomicAdd(&hist[u0 >> 4], 1u); c1++; }
      if (u1 >= 0x3F80u) { atomicAdd(&hist[u1 >> 4], 1u); c1++; }
    }
  }
#pragma unroll
  for (int o = 16; o; o >>= 1) c1 += __shfl_xor_sync(0xffffffff, c1, o);
  if ((tid & 31) == 0) atomicAdd(&s_c1, c1);
  __syncthreads();

  if (tid == 0) {
    if (s_c1 >= CRANK) {
      unsigned cum = 0;
      for (int b = 4095; b >= 0; b--) {
        unsigned h = hist[b];
        if (cum + h >= CRANK) { s_binA = (unsigned)b; s_needA = CRANK - cum; break; }
        cum += h;
      }
    } else {
      s_binA = 0xFFFFFFFFu;
      s_thr = 1u;
    }
  }
  __syncthreads();
  const unsigned binA = s_binA;

  if (binA != 0xFFFFFFFFu) {
    for (int i = tid; i < DHID / 8; i += 256) {
      uint4 v = xr4[i];
      unsigned w[4] = {v.x, v.y, v.z, v.w};
#pragma unroll
      for (int q = 0; q < 4; q++) {
        unsigned u0 = w[q] & 0xFFFFu, u1 = w[q] >> 16;
        if ((u0 >> 4) == binA) atomicAdd(&hist16[u0 & 15u], 1u);
        if ((u1 >> 4) == binA) atomicAdd(&hist16[u1 & 15u], 1u);
      }
    }
    __syncthreads();
    if (tid == 0) {
      unsigned cum = 0, need = s_needA;
      unsigned thr = binA << 4;
      for (int b = 15; b >= 0; b--) {
        unsigned h = hist16[b];
        if (cum + h >= need) { thr = (binA << 4) | (unsigned)b; break; }
        cum += h;
      }
      s_thr = thr;
    }
    __syncthreads();
  }
  const unsigned thr = s_thr;

  for (int i = tid; i < DHID / 8; i += 256) {
    uint4 v = xr4[i];
    unsigned w[4] = {v.x, v.y, v.z, v.w};
#pragma unroll
    for (int q = 0; q < 4; q++) {
      unsigned u0 = w[q] & 0xFFFFu, u1 = w[q] >> 16;
      if (u0 >= thr && u0 != 0) {
        int p = atomicAdd(&s_cc, 1);
        if (p < NCAND) g_cand[(size_t)row * NCAND + p] = i * 8 + q * 2;
      }
      if (u1 >= thr && u1 != 0) {
        int p = atomicAdd(&s_cc, 1);
        if (p < NCAND) g_cand[(size_t)row * NCAND + p] = i * 8 + q * 2 + 1;
      }
    }
  }
  __syncthreads();
  if (tid == 0) g_ccnt[row] = (s_cc < NCAND) ? s_cc : NCAND;
}

// ---------------- kernel 4: R1-identical fp32 rescore + exact top-64 -----------
__global__ __launch_bounds__(256) void exact_kernel(const float* __restrict__ embs,
                                                    const float* __restrict__ W,
                                                    const float* __restrict__ bup) {
  __shared__ float ar[DEMB];
  __shared__ float sval[NCAND];
  __shared__ int   sidx[NCAND];
  const int row = blockIdx.x, tid = threadIdx.x;

  for (int i = tid; i < DEMB; i += 256) ar[i] = embs[(size_t)row * DEMB + i];
  sval[tid] = -1e30f;
  sidx[tid] = 0;
  __syncthreads();

  const int cnt = g_ccnt[row];
  if (tid < cnt) {
    const int h = g_cand[(size_t)row * NCAND + tid];
    const float4* wr4 = reinterpret_cast<const float4*>(W + (size_t)h * DEMB);
    float acc = 0.f;
#pragma unroll 4
    for (int kk = 0; kk < DEMB / 4; kk++) {
      float4 w = __ldg(wr4 + kk);
      const int k = kk * 4;
      acc = __fmaf_rn(ar[k + 0], w.x, acc);
      acc = __fmaf_rn(ar[k + 1], w.y, acc);
      acc = __fmaf_rn(ar[k + 2], w.z, acc);
      acc = __fmaf_rn(ar[k + 3], w.w, acc);
    }
    sval[tid] = fmaxf(acc + __ldg(bup + h), 0.f);
    sidx[tid] = h;
  }
  __syncthreads();

  for (int k = 2; k <= NCAND; k <<= 1) {
    for (int j = k >> 1; j > 0; j >>= 1) {
      int ixj = tid ^ j;
      if (ixj > tid) {
        bool up = ((tid & k) == 0);
        float va = sval[tid], vb = sval[ixj];
        bool sw = up ? (va > vb) : (va < vb);
        if (sw) {
          sval[tid] = vb; sval[ixj] = va;
          int t = sidx[tid]; sidx[tid] = sidx[ixj]; sidx[ixj] = t;
        }
      }
      __syncthreads();
    }
  }

  float thr = sval[191];
  if (tid >= 192) {
    int j = tid - 192;
    bool keep = sval[tid] > thr;
    g_val[row * TOPK + j] = keep ? sval[tid] : 0.f;
    g_idx[row * TOPK + j] = keep ? sidx[tid] : 0;
  }
}

// ---------------- kernel 5: sparse decoder -------------------------------------
__global__ __launch_bounds__(384) void decoder_kernel(
    const float* __restrict__ bdown, float* __restrict__ out) {
  const int b = blockIdx.x;
  const int tid = threadIdx.x;
  __shared__ int   sidx[TOPK];
  __shared__ float sval[TOPK];
  if (tid < TOPK) {
    sidx[tid] = g_idx[b * TOPK + tid];
    sval[tid] = g_val[b * TOPK + tid];
  }
  __syncthreads();

  for (int k = 2; k <= TOPK; k <<= 1) {
    for (int j = k >> 1; j > 0; j >>= 1) {
      if (tid < TOPK) {
        int ixj = tid ^ j;
        if (ixj > tid) {
          bool up = ((tid & k) == 0);
          int ia = sidx[tid], ib = sidx[ixj];
          bool sw = up ? (ia > ib) : (ia < ib);
          if (sw) {
            sidx[tid] = ib; sidx[ixj] = ia;
            float fa = sval[tid]; sval[tid] = sval[ixj]; sval[ixj] = fa;
          }
        }
      }
      __syncthreads();
    }
  }

  const int e0 = tid, e1 = tid + 384, e2 = tid + 768;
  float a0 = bdown[e0], a1 = bdown[e1], a2 = bdown[e2];
#pragma unroll 4
  for (int k = 0; k < TOPK; k++) {
    float v = sval[k];
    const float* wr = g_wdt + (size_t)sidx[k] * DEMB;
    a0 = fmaf(v, wr[e0], a0);
    a1 = fmaf(v, wr[e1], a1);
    a2 = fmaf(v, wr[e2], a2);
  }
  float* o = out + (size_t)b * DEMB;
  o[e0] = a0; o[e1] = a1; o[e2] = a2;
}

// ---------------- launch -------------------------------------------------------
extern "C" void kernel_launch(void* const* d_in, const int* in_sizes, int n_in,
                              void* d_out, int out_size) {
  const float* embs   = (const float*)d_in[0];
  const float* W_up   = (const float*)d_in[1];
  const float* b_up   = (const float*)d_in[2];
  const float* W_down = (const float*)d_in[3];
  const float* b_down = (const float*)d_in[4];
  float* out = (float*)d_out;

  cudaFuncSetAttribute(gemm_bf16_kernel,
                       cudaFuncAttributeMaxDynamicSharedMemorySize, GEMM_SMEM);

  cvt_A_kernel<<<(BROWS * DEMB) / (256 * 8), 256>>>(embs);
  cvt_W_kernel<<<((size_t)DHID * DEMB) / (256 * 8), 256>>>(W_up);
  transpose_kernel<<<dim3(DHID / 32, DEMB / 32), dim3(32, 8)>>>(W_down);

  gemm_bf16_kernel<<<dim3(BROWS / BM, DHID / BN), GTHREADS, GEMM_SMEM>>>(b_up);

  select_kernel<<<BROWS, 256>>>();
  exact_kernel<<<BROWS, 256>>>(embs, W_up, b_up);
  decoder_kernel<<<BROWS, 384>>>(b_down, out);
}

// round 13
// speedup vs baseline: 4.2030x; 1.0951x over previous
#include <cuda_runtime.h>
#include <cuda_bf16.h>
#include <cstdint>
#include <cstddef>

#define BROWS 8192
#define DEMB  1152
#define DHID  32768
#define TOPK  64
#define NCAND 256
#define CRANK 97

// GEMM tiling — 2 CTAs/SM
#define BM 128
#define BN 128
#define BK 64
#define STAGES 3
#define KITERS 18                  // 1152/64
#define LDB 144                    // padded row bytes (128 data + 16) — conflict-free LDSM
#define STAGE_B ((BM + BN) * LDB)  // 36864
#define GEMM_SMEM (STAGES * STAGE_B)  // 110592 -> 2 CTAs (221K < 228K)
#define GTHREADS 256

// ---------------- scratch (referenced from DEVICE code only) -------------------
static __device__ __nv_bfloat16 g_ab[(size_t)BROWS * DEMB];
static __device__ __nv_bfloat16 g_wb[(size_t)DHID * DEMB];
static __device__ __nv_bfloat16 g_xb[(size_t)BROWS * DHID];   // approx acts
static __device__ float g_wdt[(size_t)DHID * DEMB];           // W_down^T
static __device__ int   g_cand[(size_t)BROWS * NCAND];
static __device__ int   g_ccnt[BROWS];
static __device__ float g_val[BROWS * TOPK];
static __device__ int   g_idx[BROWS * TOPK];

// ---------------- helpers ------------------------------------------------------
__device__ __forceinline__ uint32_t smem_u32(const void* p) {
  uint32_t a;
  asm("{ .reg .u64 t; cvta.to.shared.u64 t, %1; cvt.u32.u64 %0, t; }" : "=r"(a) : "l"(p));
  return a;
}
__device__ __forceinline__ void cp16(uint32_t dst, const void* src) {
  asm volatile("cp.async.cg.shared.global [%0], [%1], 16;" :: "r"(dst), "l"(src));
}
__device__ __forceinline__ void ldsm4(uint32_t* r, uint32_t addr) {
  asm volatile("ldmatrix.sync.aligned.m8n8.x4.shared.b16 {%0,%1,%2,%3}, [%4];"
               : "=r"(r[0]), "=r"(r[1]), "=r"(r[2]), "=r"(r[3]) : "r"(addr) : "memory");
}
__device__ __forceinline__ void mma16816(float* c, const uint32_t* a,
                                         uint32_t b0, uint32_t b1) {
  asm volatile("mma.sync.aligned.m16n8k16.row.col.f32.bf16.bf16.f32 "
               "{%0,%1,%2,%3}, {%4,%5,%6,%7}, {%8,%9}, {%0,%1,%2,%3};"
               : "+f"(c[0]), "+f"(c[1]), "+f"(c[2]), "+f"(c[3])
               : "r"(a[0]), "r"(a[1]), "r"(a[2]), "r"(a[3]), "r"(b0), "r"(b1));
}
__device__ __forceinline__ void cvt8(const float* __restrict__ src,
                                     __nv_bfloat16* __restrict__ dst, size_t i) {
  float4 a = *reinterpret_cast<const float4*>(src + i);
  float4 b = *reinterpret_cast<const float4*>(src + i + 4);
  __nv_bfloat162 p[4];
  p[0] = __float22bfloat162_rn(make_float2(a.x, a.y));
  p[1] = __float22bfloat162_rn(make_float2(a.z, a.w));
  p[2] = __float22bfloat162_rn(make_float2(b.x, b.y));
  p[3] = __float22bfloat162_rn(make_float2(b.z, b.w));
  *reinterpret_cast<uint4*>(dst + i) = *reinterpret_cast<uint4*>(p);
}

// ---------------- kernel 0a/0b: fp32 -> bf16 ------------------------------------
__global__ void cvt_A_kernel(const float* __restrict__ src) {
  size_t i = ((size_t)blockIdx.x * blockDim.x + threadIdx.x) * 8;
  cvt8(src, g_ab, i);
}
__global__ void cvt_W_kernel(const float* __restrict__ src) {
  size_t i = ((size_t)blockIdx.x * blockDim.x + threadIdx.x) * 8;
  cvt8(src, g_wb, i);
}

// ---------------- kernel 1: bf16 mma.sync GEMM, 128x128x64, 3-stage, 2 CTA/SM --
// K-loop unrolled x3: stage index compile-time; all smem offsets loop-invariant.
__global__ __launch_bounds__(GTHREADS, 2) void gemm_bf16_kernel(const float* __restrict__ bias) {
  extern __shared__ __align__(128) char smem[];
  const uint32_t sb = smem_u32(smem);
  const int tid = threadIdx.x, lane = tid & 31, wid = tid >> 5;
  const int bm = blockIdx.x, bn = blockIdx.y;
  const int wm = wid >> 1, wn = wid & 1;   // 4x2 warps, warp tile 32x64

  // loader: per-thread fixed src pointers + smem dst bases per stage
  const int lrow = tid >> 3, lkc = tid & 7;
  const __nv_bfloat16* srcA = g_ab + (size_t)(bm * BM + lrow) * DEMB + lkc * 8;
  const __nv_bfloat16* srcB = g_wb + (size_t)(bn * BN + lrow) * DEMB + lkc * 8;
  const uint32_t dstoff = lrow * LDB + lkc * 16;
  const uint32_t lst[STAGES] = {sb + dstoff, sb + STAGE_B + dstoff,
                                sb + 2 * STAGE_B + dstoff};

  // compute warps: loop-invariant fragment offsets
  const uint32_t rsel = (lane & 15);
  const uint32_t ksel = (lane >> 4) * 16;
  const uint32_t aoff0 = (wm * 32 + rsel) * LDB + ksel;
  const uint32_t aoff1 = aoff0 + 16 * LDB;
  const uint32_t boff0 = BM * LDB + (wn * 64 + rsel) * LDB + ksel;
  const uint32_t boff1 = boff0 + 16 * LDB;
  const uint32_t boff2 = boff0 + 32 * LDB;
  const uint32_t boff3 = boff0 + 48 * LDB;
  const uint32_t stg[STAGES] = {sb, sb + STAGE_B, sb + 2 * STAGE_B};

  float acc[2][8][4];
#pragma unroll
  for (int i = 0; i < 2; i++)
#pragma unroll
    for (int j = 0; j < 8; j++)
#pragma unroll
      for (int q = 0; q < 4; q++) acc[i][j][q] = 0.f;

#define LOAD_STAGE(DSTG, IT)                                                \
  do {                                                                      \
    int _it = (IT);                                                         \
    if (_it < KITERS) {                                                     \
      uint32_t ab = lst[DSTG];                                              \
      const __nv_bfloat16* sa = srcA + _it * BK;                            \
      const __nv_bfloat16* sbp = srcB + _it * BK;                           \
      _Pragma("unroll")                                                     \
      for (int j = 0; j < 4; j++) {                                         \
        cp16(ab + j * (32 * LDB), sa + (size_t)j * 32 * DEMB);              \
        cp16(ab + BM * LDB + j * (32 * LDB), sbp + (size_t)j * 32 * DEMB);  \
      }                                                                     \
    }                                                                       \
    asm volatile("cp.async.commit_group;" ::: "memory");                    \
  } while (0)

#define GEMM_BODY(S, ITER)                                                  \
  do {                                                                      \
    asm volatile("cp.async.wait_group 1;" ::: "memory");                    \
    __syncthreads();                                                        \
    const uint32_t Sb = stg[S];                                             \
    _Pragma("unroll")                                                       \
    for (int ks = 0; ks < 4; ++ks) {                                        \
      const uint32_t koff = ks * 32;                                        \
      uint32_t afr[2][4];                                                   \
      ldsm4(afr[0], Sb + aoff0 + koff);                                     \
      ldsm4(afr[1], Sb + aoff1 + koff);                                     \
      uint32_t bfr[4][4];                                                   \
      ldsm4(bfr[0], Sb + boff0 + koff);                                     \
      ldsm4(bfr[1], Sb + boff1 + koff);                                     \
      ldsm4(bfr[2], Sb + boff2 + koff);                                     \
      ldsm4(bfr[3], Sb + boff3 + koff);                                     \
      _Pragma("unroll")                                                     \
      for (int mi = 0; mi < 2; mi++)                                        \
        _Pragma("unroll")                                                   \
        for (int nj = 0; nj < 4; nj++) {                                    \
          mma16816(acc[mi][2 * nj],     afr[mi], bfr[nj][0], bfr[nj][2]);   \
          mma16816(acc[mi][2 * nj + 1], afr[mi], bfr[nj][1], bfr[nj][3]);   \
        }                                                                   \
    }                                                                       \
    LOAD_STAGE((S + 2) % STAGES, (ITER) + 2);                               \
  } while (0)

  LOAD_STAGE(0, 0);
  LOAD_STAGE(1, 1);

#pragma unroll 1
  for (int it3 = 0; it3 < KITERS; it3 += 3) {
    GEMM_BODY(0, it3);
    GEMM_BODY(1, it3 + 1);
    GEMM_BODY(2, it3 + 2);
  }

  // epilogue: bias + relu + bf16 store
  const int mrow0 = bm * BM + wm * 32;
  const int ncol0 = bn * BN + wn * 64;
#pragma unroll
  for (int nn = 0; nn < 8; nn++) {
    const int col = ncol0 + nn * 8 + 2 * (lane & 3);
    const float2 bv = *reinterpret_cast<const float2*>(bias + col);
#pragma unroll
    for (int mi = 0; mi < 2; mi++) {
      const int r0 = mrow0 + mi * 16 + (lane >> 2);
      float v0 = fmaxf(acc[mi][nn][0] + bv.x, 0.f);
      float v1 = fmaxf(acc[mi][nn][1] + bv.y, 0.f);
      float v2 = fmaxf(acc[mi][nn][2] + bv.x, 0.f);
      float v3 = fmaxf(acc[mi][nn][3] + bv.y, 0.f);
      __nv_bfloat162 p0 = __float22bfloat162_rn(make_float2(v0, v1));
      __nv_bfloat162 p1 = __float22bfloat162_rn(make_float2(v2, v3));
      *reinterpret_cast<uint32_t*>(g_xb + (size_t)r0 * DHID + col) =
          *reinterpret_cast<uint32_t*>(&p0);
      *reinterpret_cast<uint32_t*>(g_xb + (size_t)(r0 + 8) * DHID + col) =
          *reinterpret_cast<uint32_t*>(&p1);
    }
  }
}

// ---------------- kernel 2: transpose W_down -----------------------------------
__global__ void transpose_kernel(const float* __restrict__ W) {
  __shared__ float tile[32][33];
  int x = blockIdx.x * 32 + threadIdx.x;
  int y = blockIdx.y * 32 + threadIdx.y;
#pragma unroll
  for (int j = 0; j < 32; j += 8)
    tile[threadIdx.y + j][threadIdx.x] = W[(size_t)(y + j) * DHID + x];
  __syncthreads();
  int xo = blockIdx.y * 32 + threadIdx.x;
  int yo = blockIdx.x * 32 + threadIdx.y;
#pragma unroll
  for (int j = 0; j < 32; j += 8)
    g_wdt[(size_t)(yo + j) * DEMB + xo] = tile[threadIdx.x][threadIdx.y + j];
}

// ---------------- kernel 3: candidate selection — 2 sweeps ----------------------
// Sweep 1: 4096-bin hist (u>>4) over x-hat >= 1.0; find coarse bin where the
// top-down cumulative count reaches CRANK. Sweep 2: compact ALL u >= binA<<4 —
// a superset of the exact rank-CRANK cut (count <= CRANK + hist[binA] << NCAND).
__global__ __launch_bounds__(256) void select_kernel() {
  __shared__ unsigned hist[4096];
  __shared__ int s_c1, s_cc;
  __shared__ unsigned s_thr;

  const int row = blockIdx.x, tid = threadIdx.x;
  const uint4* xr4 = reinterpret_cast<const uint4*>(g_xb + (size_t)row * DHID);

  for (int i = tid; i < 4096; i += 256) hist[i] = 0;
  if (tid == 0) { s_c1 = 0; s_cc = 0; }
  __syncthreads();

  int c1 = 0;
  for (int i = tid; i < DHID / 8; i += 256) {
    uint4 v = xr4[i];
    unsigned w[4] = {v.x, v.y, v.z, v.w};
#pragma unroll
    for (int q = 0; q < 4; q++) {
      unsigned u0 = w[q] & 0xFFFFu, u1 = w[q] >> 16;
      if (u0 >= 0x3F80u) { atomicAdd(&hist[u0 >> 4], 1u); c1++; }
      if (u1 >= 0x3F80u) { atomicAdd(&hist[u1 >> 4], 1u); c1++; }
    }
  }
#pragma unroll
  for (int o = 16; o; o >>= 1) c1 += __shfl_xor_sync(0xffffffff, c1, o);
  if ((tid & 31) == 0) atomicAdd(&s_c1, c1);
  __syncthreads();

  if (tid == 0) {
    if (s_c1 >= CRANK) {
      unsigned cum = 0, thr = 0x3F80u;
      for (int b = 4095; b >= 0; b--) {
        cum += hist[b];
        if (cum >= CRANK) { thr = (unsigned)b << 4; break; }
      }
      s_thr = thr;
    } else {
      s_thr = 1u;               // degenerate: take all positives
    }
  }
  __syncthreads();
  const unsigned thr = s_thr;

  for (int i = tid; i < DHID / 8; i += 256) {
    uint4 v = xr4[i];
    unsigned w[4] = {v.x, v.y, v.z, v.w};
#pragma unroll
    for (int q = 0; q < 4; q++) {
      unsigned u0 = w[q] & 0xFFFFu, u1 = w[q] >> 16;
      if (u0 >= thr && u0 != 0) {
        int p = atomicAdd(&s_cc, 1);
        if (p < NCAND) g_cand[(size_t)row * NCAND + p] = i * 8 + q * 2;
      }
      if (u1 >= thr && u1 != 0) {
        int p = atomicAdd(&s_cc, 1);
        if (p < NCAND) g_cand[(size_t)row * NCAND + p] = i * 8 + q * 2 + 1;
      }
    }
  }
  __syncthreads();
  if (tid == 0) g_ccnt[row] = (s_cc < NCAND) ? s_cc : NCAND;
}

// ---------------- kernel 4: R1-identical fp32 rescore + exact top-64 -----------
__global__ __launch_bounds__(256) void exact_kernel(const float* __restrict__ embs,
                                                    const float* __restrict__ W,
                                                    const float* __restrict__ bup) {
  __shared__ float ar[DEMB];
  __shared__ float sval[NCAND];
  __shared__ int   sidx[NCAND];
  const int row = blockIdx.x, tid = threadIdx.x;

  for (int i = tid; i < DEMB; i += 256) ar[i] = embs[(size_t)row * DEMB + i];
  sval[tid] = -1e30f;
  sidx[tid] = 0;
  __syncthreads();

  const int cnt = g_ccnt[row];
  if (tid < cnt) {
    const int h = g_cand[(size_t)row * NCAND + tid];
    const float4* wr4 = reinterpret_cast<const float4*>(W + (size_t)h * DEMB);
    float acc = 0.f;
#pragma unroll 4
    for (int kk = 0; kk < DEMB / 4; kk++) {
      float4 w = __ldg(wr4 + kk);
      const int k = kk * 4;
      acc = __fmaf_rn(ar[k + 0], w.x, acc);
      acc = __fmaf_rn(ar[k + 1], w.y, acc);
      acc = __fmaf_rn(ar[k + 2], w.z, acc);
      acc = __fmaf_rn(ar[k + 3], w.w, acc);
    }
    sval[tid] = fmaxf(acc + __ldg(bup + h), 0.f);
    sidx[tid] = h;
  }
  __syncthreads();

  for (int k = 2; k <= NCAND; k <<= 1) {
    for (int j = k >> 1; j > 0; j >>= 1) {
      int ixj = tid ^ j;
      if (ixj > tid) {
        bool up = ((tid & k) == 0);
        float va = sval[tid], vb = sval[ixj];
        bool sw = up ? (va > vb) : (va < vb);
        if (sw) {
          sval[tid] = vb; sval[ixj] = va;
          int t = sidx[tid]; sidx[tid] = sidx[ixj]; sidx[ixj] = t;
        }
      }
      __syncthreads();
    }
  }

  float thr = sval[191];
  if (tid >= 192) {
    int j = tid - 192;
    bool keep = sval[tid] > thr;
    g_val[row * TOPK + j] = keep ? sval[tid] : 0.f;
    g_idx[row * TOPK + j] = keep ? sidx[tid] : 0;
  }
}

// ---------------- kernel 5: sparse decoder -------------------------------------
__global__ __launch_bounds__(384) void decoder_kernel(
    const float* __restrict__ bdown, float* __restrict__ out) {
  const int b = blockIdx.x;
  const int tid = threadIdx.x;
  __shared__ int   sidx[TOPK];
  __shared__ float sval[TOPK];
  if (tid < TOPK) {
    sidx[tid] = g_idx[b * TOPK + tid];
    sval[tid] = g_val[b * TOPK + tid];
  }
  __syncthreads();

  for (int k = 2; k <= TOPK; k <<= 1) {
    for (int j = k >> 1; j > 0; j >>= 1) {
      if (tid < TOPK) {
        int ixj = tid ^ j;
        if (ixj > tid) {
          bool up = ((tid & k) == 0);
          int ia = sidx[tid], ib = sidx[ixj];
          bool sw = up ? (ia > ib) : (ia < ib);
          if (sw) {
            sidx[tid] = ib; sidx[ixj] = ia;
            float fa = sval[tid]; sval[tid] = sval[ixj]; sval[ixj] = fa;
          }
        }
      }
      __syncthreads();
    }
  }

  const int e0 = tid, e1 = tid + 384, e2 = tid + 768;
  float a0 = bdown[e0], a1 = bdown[e1], a2 = bdown[e2];
#pragma unroll 4
  for (int k = 0; k < TOPK; k++) {
    float v = sval[k];
    const float* wr = g_wdt + (size_t)sidx[k] * DEMB;
    a0 = fmaf(v, wr[e0], a0);
    a1 = fmaf(v, wr[e1], a1);
    a2 = fmaf(v, wr[e2], a2);
  }
  float* o = out + (size_t)b * DEMB;
  o[e0] = a0; o[e1] = a1; o[e2] = a2;
}

// ---------------- launch -------------------------------------------------------
extern "C" void kernel_launch(void* const* d_in, const int* in_sizes, int n_in,
                              void* d_out, int out_size) {
  const float* embs   = (const float*)d_in[0];
  const float* W_up   = (const float*)d_in[1];
  const float* b_up   = (const float*)d_in[2];
  const float* W_down = (const float*)d_in[3];
  const float* b_down = (const float*)d_in[4];
  float* out = (float*)d_out;

  cudaFuncSetAttribute(gemm_bf16_kernel,
                       cudaFuncAttributeMaxDynamicSharedMemorySize, GEMM_SMEM);

  cvt_A_kernel<<<(BROWS * DEMB) / (256 * 8), 256>>>(embs);
  cvt_W_kernel<<<((size_t)DHID * DEMB) / (256 * 8), 256>>>(W_up);
  transpose_kernel<<<dim3(DHID / 32, DEMB / 32), dim3(32, 8)>>>(W_down);

  gemm_bf16_kernel<<<dim3(BROWS / BM, DHID / BN), GTHREADS, GEMM_SMEM>>>(b_up);

  select_kernel<<<BROWS, 256>>>();
  exact_kernel<<<BROWS, 256>>>(embs, W_up, b_up);
  decoder_kernel<<<BROWS, 384>>>(b_down, out);
}